// round 12
// baseline (speedup 1.0000x reference)
#include <cuda_runtime.h>
#include <cuda_fp16.h>
#include <cstdint>

#define D_MODEL 1024
#define NHEADS  16
#define HDIM    64
#define BATCH   2
#define SEQ     2048
#define NROWS   (BATCH * SEQ)     // 4096
#define KDIM    D_MODEL

// softmax scale folded into Q projection: 1/sqrt(64) * log2(e)
#define QK_SCALE 0.1803368801111244f

// ---------------------------------------------------------------------------
// Scratch (device globals)
// ---------------------------------------------------------------------------
__device__ __half g_Hh [NROWS * D_MODEL];   // H, also V in attention
__device__ __half g_Qh [NROWS * D_MODEL];
__device__ __half g_Kh [NROWS * D_MODEL];
__device__ __half g_AOh[NROWS * D_MODEL];
__device__ __half g_Wqh[D_MODEL * D_MODEL];
__device__ __half g_Wkh[D_MODEL * D_MODEL];
__device__ __half g_Woh[D_MODEL * D_MODEL];

// ---------------------------------------------------------------------------
// helpers
// ---------------------------------------------------------------------------
__device__ __forceinline__ uint32_t smem_to_u32(const void* p) {
    uint32_t a;
    asm("{ .reg .u64 t; cvta.to.shared.u64 t, %1; cvt.u32.u64 %0, t; }"
        : "=r"(a) : "l"(p));
    return a;
}
__device__ __forceinline__ void ldsm_x4(uint32_t& r0, uint32_t& r1,
                                        uint32_t& r2, uint32_t& r3, uint32_t addr) {
    asm volatile("ldmatrix.sync.aligned.m8n8.x4.shared.b16 {%0,%1,%2,%3}, [%4];"
                 : "=r"(r0), "=r"(r1), "=r"(r2), "=r"(r3) : "r"(addr));
}
__device__ __forceinline__ void ldsm_x4_t(uint32_t& r0, uint32_t& r1,
                                          uint32_t& r2, uint32_t& r3, uint32_t addr) {
    asm volatile("ldmatrix.sync.aligned.m8n8.x4.trans.shared.b16 {%0,%1,%2,%3}, [%4];"
                 : "=r"(r0), "=r"(r1), "=r"(r2), "=r"(r3) : "r"(addr));
}
__device__ __forceinline__ void mma16816(float* c, const uint32_t* a,
                                         const uint32_t* b) {
    asm volatile(
        "mma.sync.aligned.m16n8k16.row.col.f32.f16.f16.f32 "
        "{%0,%1,%2,%3}, {%4,%5,%6,%7}, {%8,%9}, {%0,%1,%2,%3};"
        : "+f"(c[0]), "+f"(c[1]), "+f"(c[2]), "+f"(c[3])
        : "r"(a[0]), "r"(a[1]), "r"(a[2]), "r"(a[3]), "r"(b[0]), "r"(b[1]));
}
// fp16-accumulator variant: C/D are 2 packed-half2 registers
__device__ __forceinline__ void mma16816h(uint32_t* c, const uint32_t* a,
                                          const uint32_t* b) {
    asm volatile(
        "mma.sync.aligned.m16n8k16.row.col.f16.f16.f16.f16 "
        "{%0,%1}, {%2,%3,%4,%5}, {%6,%7}, {%0,%1};"
        : "+r"(c[0]), "+r"(c[1])
        : "r"(a[0]), "r"(a[1]), "r"(a[2]), "r"(a[3]), "r"(b[0]), "r"(b[1]));
}
__device__ __forceinline__ float ex2f(float x) {
    float r;
    asm("ex2.approx.ftz.f32 %0, %1;" : "=f"(r) : "f"(x));
    return r;
}
__device__ __forceinline__ uint32_t packh2(float a, float b) {
    __half2 t = __floats2half2_rn(a, b);
    return *(uint32_t*)&t;
}
__device__ __forceinline__ void cp16(uint32_t smem, const void* g) {
    asm volatile("cp.async.cg.shared.global [%0], [%1], 16;"
                 :: "r"(smem), "l"(g) : "memory");
}
#define CP_COMMIT() asm volatile("cp.async.commit_group;" ::: "memory")
#define CP_WAIT0()  asm volatile("cp.async.wait_group 0;" ::: "memory")
#define CP_WAIT1()  asm volatile("cp.async.wait_group 1;" ::: "memory")

// ---------------------------------------------------------------------------
// fp32 -> fp16 cast, 4 tensors in one launch
// ---------------------------------------------------------------------------
__device__ __forceinline__ void cast4_do(const float4* src, uint2* hi, int i)
{
    float4 v = src[i];
    hi[i] = make_uint2(packh2(v.x, v.y), packh2(v.z, v.w));
}

__global__ __launch_bounds__(256)
void cast4_kernel(const float4* s0, uint2* h0, int n0,
                  const float4* s1, uint2* h1, int n1,
                  const float4* s2, uint2* h2, int n2,
                  const float4* s3, uint2* h3, int n3)
{
    int i = blockIdx.x * blockDim.x + threadIdx.x;
    if (i < n0) { cast4_do(s0, h0, i); return; }
    i -= n0;
    if (i < n1) { cast4_do(s1, h1, i); return; }
    i -= n1;
    if (i < n2) { cast4_do(s2, h2, i); return; }
    i -= n2;
    if (i < n3) { cast4_do(s3, h3, i); }
}

// ---------------------------------------------------------------------------
// HMMA GEMM (1-pass fp16): C = A*W^T + bias.
// F16ACC: accumulate in fp16, flush to fp32 every 2 k-iters.
// CTA 128x128, BK=64, 256 threads (8 warps), 3-stage cp.async pipeline.
// ---------------------------------------------------------------------------
#define BM 128
#define BN 128
#define BKK 64
#define LDT 72                     // 144 B row (9 x 16B) -> LDSM conflict-free
#define GTILE (BM * LDT * 2)       // 18432 B per array
#define GST   (2 * GTILE)          // A + W per stage
#define GNIT  (KDIM / BKK)         // 16

template <bool F16ACC>
__device__ __forceinline__ void gemm_core(
    const __half* __restrict__ A, const __half* __restrict__ W,
    const float* __restrict__ bias, float scale,
    float* __restrict__ Cf, __half* __restrict__ Ch)
{
    extern __shared__ char dsm[];
    __shared__ float s_bias[BN];

    const int tid = threadIdx.x;
    const int wid = tid >> 5;
    const int lid = tid & 31;
    const int wm  = wid & 1;
    const int wn  = wid >> 1;
    const int m0  = blockIdx.y * BM;
    const int n0  = blockIdx.x * BN;

    if (tid < BN) s_bias[tid] = bias[n0 + tid];

    const int lr     = lid & 7;
    const int half2_ = (lid >> 3) & 1;
    const int kh     = (lid >> 4) & 1;
    const int mbase  = wm * 64;
    const int nbase  = wn * 32;

    const uint32_t smem_base = smem_to_u32(dsm);

    float acc[4][4][4];
#pragma unroll
    for (int i = 0; i < 4; i++)
#pragma unroll
        for (int j = 0; j < 4; j++)
#pragma unroll
            for (int c = 0; c < 4; c++) acc[i][j][c] = 0.0f;

    uint32_t acc16[4][4][2];
#pragma unroll
    for (int i = 0; i < 4; i++)
#pragma unroll
        for (int j = 0; j < 4; j++) { acc16[i][j][0] = 0u; acc16[i][j][1] = 0u; }

    auto load_stage = [&](int k0, int s) {
        uint32_t sb = smem_base + s * GST;
#pragma unroll
        for (int it = 0; it < 8; it++) {
            int e    = tid + it * 256;      // 0..2047
            int arr  = e >> 10;             // 0 A, 1 W
            int rem  = e & 1023;
            int row  = rem >> 3;
            int c    = rem & 7;
            const __half* g = (arr == 0)
                ? A + (size_t)(m0 + row) * KDIM + k0 + c * 8
                : W + (size_t)(n0 + row) * KDIM + k0 + c * 8;
            cp16(sb + arr * GTILE + row * (LDT * 2) + c * 16, g);
        }
        CP_COMMIT();
    };

    load_stage(0, 0);
    load_stage(BKK, 1);

    for (int i = 0; i < GNIT; i++) {
        if (i + 1 < GNIT) { CP_WAIT1(); } else { CP_WAIT0(); }
        __syncthreads();
        if (i + 2 < GNIT) load_stage((i + 2) * BKK, (i + 2) % 3);

        const uint32_t sb = smem_base + (i % 3) * GST;
        const uint32_t uA = sb;
        const uint32_t uW = sb + GTILE;

#pragma unroll
        for (int ks = 0; ks < 4; ks++) {
            const int kcol = ks * 16 + kh * 8;

            uint32_t af[4][4];
#pragma unroll
            for (int mt = 0; mt < 4; mt++) {
                int row = mbase + mt * 16 + lr + 8 * half2_;
                ldsm_x4(af[mt][0], af[mt][1], af[mt][2], af[mt][3],
                        uA + (uint32_t)(row * LDT + kcol) * 2);
            }
            uint32_t bf[4][2];
#pragma unroll
            for (int ntp = 0; ntp < 2; ntp++) {
                int row = nbase + ntp * 16 + lr + 8 * half2_;
                uint32_t r0, r1, r2, r3;
                ldsm_x4(r0, r1, r2, r3, uW + (uint32_t)(row * LDT + kcol) * 2);
                bf[ntp * 2 + 0][0] = r0; bf[ntp * 2 + 0][1] = r2;
                bf[ntp * 2 + 1][0] = r1; bf[ntp * 2 + 1][1] = r3;
            }
            if (F16ACC) {
#pragma unroll
                for (int mt = 0; mt < 4; mt++)
#pragma unroll
                    for (int nt = 0; nt < 4; nt++)
                        mma16816h(acc16[mt][nt], af[mt], bf[nt]);
            } else {
#pragma unroll
                for (int mt = 0; mt < 4; mt++)
#pragma unroll
                    for (int nt = 0; nt < 4; nt++)
                        mma16816(acc[mt][nt], af[mt], bf[nt]);
            }
        }

        // flush fp16 accumulators into fp32 every 2 iters
        if (F16ACC && ((i & 1) == 1 || i == GNIT - 1)) {
#pragma unroll
            for (int mt = 0; mt < 4; mt++)
#pragma unroll
                for (int nt = 0; nt < 4; nt++) {
                    float2 f0 = __half22float2(*(__half2*)&acc16[mt][nt][0]);
                    float2 f1 = __half22float2(*(__half2*)&acc16[mt][nt][1]);
                    acc[mt][nt][0] += f0.x; acc[mt][nt][1] += f0.y;
                    acc[mt][nt][2] += f1.x; acc[mt][nt][3] += f1.y;
                    acc16[mt][nt][0] = 0u;  acc16[mt][nt][1] = 0u;
                }
        }
    }

    const int erow = lid >> 2;
    const int ecol = (lid & 3) * 2;
#pragma unroll
    for (int mt = 0; mt < 4; mt++) {
#pragma unroll
        for (int nt = 0; nt < 4; nt++) {
            int gm = m0 + mbase + mt * 16 + erow;
            int nc = nbase + nt * 8 + ecol;
            int gn = n0 + nc;
            float v0 = (acc[mt][nt][0] + s_bias[nc])     * scale;
            float v1 = (acc[mt][nt][1] + s_bias[nc + 1]) * scale;
            float v2 = (acc[mt][nt][2] + s_bias[nc])     * scale;
            float v3 = (acc[mt][nt][3] + s_bias[nc + 1]) * scale;
            if (Ch) {
                *(uint32_t*)&Ch[(size_t)gm * D_MODEL + gn]       = packh2(v0, v1);
                *(uint32_t*)&Ch[(size_t)(gm + 8) * D_MODEL + gn] = packh2(v2, v3);
            } else {
                *(float2*)&Cf[(size_t)gm * D_MODEL + gn]       = make_float2(v0, v1);
                *(float2*)&Cf[(size_t)(gm + 8) * D_MODEL + gn] = make_float2(v2, v3);
            }
        }
    }
}

__global__ __launch_bounds__(256, 1)
void qk_gemm_kernel(const float* __restrict__ bq, const float* __restrict__ bk)
{
    if (blockIdx.z == 0)
        gemm_core<false>(g_Hh, g_Wqh, bq, QK_SCALE, nullptr, g_Qh);
    else
        gemm_core<false>(g_Hh, g_Wkh, bk, 1.0f, nullptr, g_Kh);
}

__global__ __launch_bounds__(256, 1)
void out_gemm_kernel(const float* __restrict__ bo, float* __restrict__ out)
{
    gemm_core<true>(g_AOh, g_Woh, bo, 1.0f, out, nullptr);
}

// ---------------------------------------------------------------------------
// HMMA flash attention: S fp32-acc, PV fp16-acc (per-tile flush).
// grid (32 = B*NH, 16 = SEQ/128), 256 threads (8 warps), 128 q-rows per CTA.
// ---------------------------------------------------------------------------
#define SLDT 72                        // 144 B row
#define ATILE (64 * SLDT * 2)          // 9216 B per array
#define AST   (2 * ATILE)              // 18432 B per stage (K, V)
#define KTILES (SEQ / 64)              // 32

__global__ __launch_bounds__(256, 1)
void attn_mma_kernel()
{
    extern __shared__ char dsm[];
    __half* pool = (__half*)dsm;

    const int tid = threadIdx.x;
    const int wid = tid >> 5;
    const int lid = tid & 31;
    const int b   = blockIdx.x >> 4;
    const int h   = blockIdx.x & 15;
    const int q0  = blockIdx.y * 128;

    const int lr     = lid & 7;
    const int half2_ = (lid >> 3) & 1;
    const int kh     = (lid >> 4) & 1;

    const uint32_t smem_base = smem_to_u32(dsm);

    // ---- stage Q tile (128 x 64) through stage-0 area, extract frags ----
#pragma unroll
    for (int i = 0; i < 4; i++) {
        int e   = tid + i * 256;            // 0..1023
        int row = e >> 3;
        int c   = e & 7;
        const __half* src = g_Qh
            + (size_t)(b * SEQ + q0 + row) * D_MODEL + h * HDIM + c * 8;
        *(uint4*)(pool + row * SLDT + c * 8) = *(const uint4*)src;
    }
    __syncthreads();

    uint32_t qh[4][4];
    {
        const int wr = wid * 16;
#pragma unroll
        for (int kc = 0; kc < 4; kc++) {
            int row = wr + lr + 8 * half2_;
            int col = kc * 16 + kh * 8;
            ldsm_x4(qh[kc][0], qh[kc][1], qh[kc][2], qh[kc][3],
                    smem_base + (uint32_t)(row * SLDT + col) * 2);
        }
    }
    __syncthreads();

    float oacc[8][4];
#pragma unroll
    for (int nt = 0; nt < 8; nt++)
#pragma unroll
        for (int c = 0; c < 4; c++) oacc[nt][c] = 0.0f;
    float mx0 = -1e30f, mx1 = -1e30f, l0 = 0.0f, l1 = 0.0f;

    auto load_stage = [&](int kt, int s) {
        const int kb = kt * 64;
        uint32_t sb = smem_base + s * AST;
#pragma unroll
        for (int i = 0; i < 4; i++) {
            int arr = i >> 1;                       // 0 K, 1 V
            int rem = ((i & 1) << 8) + tid;
            int row = rem >> 3;
            int c   = rem & 7;
            const __half* g = (arr == 0 ? g_Kh : g_Hh)
                + (size_t)(b * SEQ + kb + row) * D_MODEL + h * HDIM + c * 8;
            cp16(sb + arr * ATILE + row * (SLDT * 2) + c * 16, g);
        }
        CP_COMMIT();
    };

    load_stage(0, 0);
    load_stage(1, 1);

    for (int kt = 0; kt < KTILES; kt++) {
        if (kt + 1 < KTILES) { CP_WAIT1(); } else { CP_WAIT0(); }
        __syncthreads();
        if (kt + 2 < KTILES) load_stage(kt + 2, (kt + 2) % 3);

        const uint32_t sb = smem_base + (kt % 3) * AST;
        const uint32_t uK = sb;
        const uint32_t uV = sb + ATILE;

        // ---- S = Q K^T (fp32 acc) ----
        float S[8][4];
#pragma unroll
        for (int nt = 0; nt < 8; nt++)
#pragma unroll
            for (int c = 0; c < 4; c++) S[nt][c] = 0.0f;

#pragma unroll
        for (int kc = 0; kc < 4; kc++) {
            uint32_t kb_[8][2];
#pragma unroll
            for (int ng = 0; ng < 4; ng++) {
                int row = ng * 16 + lr + 8 * half2_;
                int col = kc * 16 + kh * 8;
                uint32_t r0, r1, r2, r3;
                ldsm_x4(r0, r1, r2, r3, uK + (uint32_t)(row * SLDT + col) * 2);
                kb_[ng * 2 + 0][0] = r0; kb_[ng * 2 + 0][1] = r2;
                kb_[ng * 2 + 1][0] = r1; kb_[ng * 2 + 1][1] = r3;
            }
#pragma unroll
            for (int nt = 0; nt < 8; nt++)
                mma16816(S[nt], qh[kc], kb_[nt]);
        }

        // ---- online softmax ----
        float tm0 = -1e30f, tm1 = -1e30f;
#pragma unroll
        for (int nt = 0; nt < 8; nt++) {
            tm0 = fmaxf(tm0, fmaxf(S[nt][0], S[nt][1]));
            tm1 = fmaxf(tm1, fmaxf(S[nt][2], S[nt][3]));
        }
        tm0 = fmaxf(tm0, __shfl_xor_sync(0xffffffffu, tm0, 1));
        tm0 = fmaxf(tm0, __shfl_xor_sync(0xffffffffu, tm0, 2));
        tm1 = fmaxf(tm1, __shfl_xor_sync(0xffffffffu, tm1, 1));
        tm1 = fmaxf(tm1, __shfl_xor_sync(0xffffffffu, tm1, 2));
        float mn0 = fmaxf(mx0, tm0), mn1 = fmaxf(mx1, tm1);
        float a0 = ex2f(mx0 - mn0), a1 = ex2f(mx1 - mn1);

        uint32_t pa[4][4];
        float rs0 = 0.0f, rs1 = 0.0f;
#pragma unroll
        for (int j = 0; j < 4; j++) {
#pragma unroll
            for (int sg = 0; sg < 2; sg++) {
                int t2 = j * 2 + sg;
                float p0 = ex2f(S[t2][0] - mn0);
                float p1 = ex2f(S[t2][1] - mn0);
                float p2 = ex2f(S[t2][2] - mn1);
                float p3 = ex2f(S[t2][3] - mn1);
                rs0 += p0 + p1;
                rs1 += p2 + p3;
                pa[j][sg * 2 + 0] = packh2(p0, p1);
                pa[j][sg * 2 + 1] = packh2(p2, p3);
            }
        }
        rs0 += __shfl_xor_sync(0xffffffffu, rs0, 1);
        rs0 += __shfl_xor_sync(0xffffffffu, rs0, 2);
        rs1 += __shfl_xor_sync(0xffffffffu, rs1, 1);
        rs1 += __shfl_xor_sync(0xffffffffu, rs1, 2);
        l0 = l0 * a0 + rs0;
        l1 = l1 * a1 + rs1;
        mx0 = mn0; mx1 = mn1;
#pragma unroll
        for (int nt = 0; nt < 8; nt++) {
            oacc[nt][0] *= a0; oacc[nt][1] *= a0;
            oacc[nt][2] *= a1; oacc[nt][3] *= a1;
        }

        // ---- O += P V (fp16 acc within tile, flush to fp32) ----
        uint32_t od[8][2];
#pragma unroll
        for (int nt = 0; nt < 8; nt++) { od[nt][0] = 0u; od[nt][1] = 0u; }

#pragma unroll
        for (int kc = 0; kc < 4; kc++) {
            uint32_t vb[8][2];
#pragma unroll
            for (int dg = 0; dg < 4; dg++) {
                int rowk = kc * 16 + lr + 8 * half2_;
                int dimc = dg * 16 + kh * 8;
                uint32_t r0, r1, r2, r3;
                ldsm_x4_t(r0, r1, r2, r3, uV + (uint32_t)(rowk * SLDT + dimc) * 2);
                vb[dg * 2 + 0][0] = r0; vb[dg * 2 + 0][1] = r1;
                vb[dg * 2 + 1][0] = r2; vb[dg * 2 + 1][1] = r3;
            }
#pragma unroll
            for (int nt = 0; nt < 8; nt++)
                mma16816h(od[nt], pa[kc], vb[nt]);
        }
#pragma unroll
        for (int nt = 0; nt < 8; nt++) {
            float2 f0 = __half22float2(*(__half2*)&od[nt][0]);
            float2 f1 = __half22float2(*(__half2*)&od[nt][1]);
            oacc[nt][0] += f0.x; oacc[nt][1] += f0.y;
            oacc[nt][2] += f1.x; oacc[nt][3] += f1.y;
        }
    }

    // ---- epilogue ----
    const float inv0 = 1.0f / l0;
    const float inv1 = 1.0f / l1;
    const int gr  = b * SEQ + q0 + wid * 16 + (lid >> 2);
    const int col = h * HDIM + (lid & 3) * 2;
#pragma unroll
    for (int nt = 0; nt < 8; nt++) {
        int gc = col + nt * 8;
        float v0 = oacc[nt][0] * inv0, v1 = oacc[nt][1] * inv0;
        float v2 = oacc[nt][2] * inv1, v3 = oacc[nt][3] * inv1;
        *(uint32_t*)&g_AOh[(size_t)gr * D_MODEL + gc]       = packh2(v0, v1);
        *(uint32_t*)&g_AOh[(size_t)(gr + 8) * D_MODEL + gc] = packh2(v2, v3);
    }
}

// ---------------------------------------------------------------------------
extern "C" void kernel_launch(void* const* d_in, const int* in_sizes, int n_in,
                              void* d_out, int out_size)
{
    (void)in_sizes; (void)n_in; (void)out_size;
    const float* H  = (const float*)d_in[0];
    const float* Wq = (const float*)d_in[1];
    const float* bq = (const float*)d_in[2];
    const float* Wk = (const float*)d_in[3];
    const float* bk = (const float*)d_in[4];
    const float* Wo = (const float*)d_in[5];
    const float* bo = (const float*)d_in[6];
    float* out = (float*)d_out;

    void *p_Hh, *p_Wqh, *p_Wkh, *p_Woh;
    cudaGetSymbolAddress(&p_Hh,  g_Hh);
    cudaGetSymbolAddress(&p_Wqh, g_Wqh);
    cudaGetSymbolAddress(&p_Wkh, g_Wkh);
    cudaGetSymbolAddress(&p_Woh, g_Woh);

    const int GSMEM = 3 * GST;    // 110,592 B
    const int ASMEM = 3 * AST;    //  55,296 B

    cudaFuncSetAttribute(qk_gemm_kernel,
                         cudaFuncAttributeMaxDynamicSharedMemorySize, GSMEM);
    cudaFuncSetAttribute(out_gemm_kernel,
                         cudaFuncAttributeMaxDynamicSharedMemorySize, GSMEM);
    cudaFuncSetAttribute(attn_mma_kernel,
                         cudaFuncAttributeMaxDynamicSharedMemorySize, ASMEM);

    const int nH4 = NROWS * D_MODEL / 4;      // 1,048,576
    const int nW4 = D_MODEL * D_MODEL / 4;    // 262,144
    const int nTot = nH4 + 3 * nW4;           // 1,835,008

    cast4_kernel<<<(nTot + 255) / 256, 256>>>(
        (const float4*)H,  (uint2*)p_Hh,  nH4,
        (const float4*)Wq, (uint2*)p_Wqh, nW4,
        (const float4*)Wk, (uint2*)p_Wkh, nW4,
        (const float4*)Wo, (uint2*)p_Woh, nW4);

    dim3 ggrid(D_MODEL / BN, NROWS / BM, 2);   // (8, 32, 2)
    qk_gemm_kernel<<<ggrid, 256, GSMEM>>>(bq, bk);

    dim3 agrid(BATCH * NHEADS, SEQ / 128);     // (32, 16)
    attn_mma_kernel<<<agrid, 256, ASMEM>>>();

    dim3 ogrid(D_MODEL / BN, NROWS / BM, 1);   // (8, 32)
    out_gemm_kernel<<<ogrid, 256, GSMEM>>>(bo, out);
}

// round 13
// speedup vs baseline: 1.0488x; 1.0488x over previous
#include <cuda_runtime.h>
#include <cuda_fp16.h>
#include <cstdint>

#define D_MODEL 1024
#define NHEADS  16
#define HDIM    64
#define BATCH   2
#define SEQ     2048
#define NROWS   (BATCH * SEQ)     // 4096
#define KDIM    D_MODEL

// softmax scale folded into Q projection: 1/sqrt(64) * log2(e)
#define QK_SCALE 0.1803368801111244f

// ---------------------------------------------------------------------------
// Scratch (device globals)
// ---------------------------------------------------------------------------
__device__ __half g_Hh [NROWS * D_MODEL];   // H, also V in attention
__device__ __half g_Qh [NROWS * D_MODEL];
__device__ __half g_Kh [NROWS * D_MODEL];
__device__ __half g_AOh[NROWS * D_MODEL];
__device__ __half g_Wqh[D_MODEL * D_MODEL];
__device__ __half g_Wkh[D_MODEL * D_MODEL];
__device__ __half g_Woh[D_MODEL * D_MODEL];

// ---------------------------------------------------------------------------
// helpers
// ---------------------------------------------------------------------------
__device__ __forceinline__ uint32_t smem_to_u32(const void* p) {
    uint32_t a;
    asm("{ .reg .u64 t; cvta.to.shared.u64 t, %1; cvt.u32.u64 %0, t; }"
        : "=r"(a) : "l"(p));
    return a;
}
__device__ __forceinline__ void ldsm_x4(uint32_t& r0, uint32_t& r1,
                                        uint32_t& r2, uint32_t& r3, uint32_t addr) {
    asm volatile("ldmatrix.sync.aligned.m8n8.x4.shared.b16 {%0,%1,%2,%3}, [%4];"
                 : "=r"(r0), "=r"(r1), "=r"(r2), "=r"(r3) : "r"(addr));
}
__device__ __forceinline__ void ldsm_x4_t(uint32_t& r0, uint32_t& r1,
                                          uint32_t& r2, uint32_t& r3, uint32_t addr) {
    asm volatile("ldmatrix.sync.aligned.m8n8.x4.trans.shared.b16 {%0,%1,%2,%3}, [%4];"
                 : "=r"(r0), "=r"(r1), "=r"(r2), "=r"(r3) : "r"(addr));
}
__device__ __forceinline__ void mma16816(float* c, const uint32_t* a,
                                         const uint32_t* b) {
    asm volatile(
        "mma.sync.aligned.m16n8k16.row.col.f32.f16.f16.f32 "
        "{%0,%1,%2,%3}, {%4,%5,%6,%7}, {%8,%9}, {%0,%1,%2,%3};"
        : "+f"(c[0]), "+f"(c[1]), "+f"(c[2]), "+f"(c[3])
        : "r"(a[0]), "r"(a[1]), "r"(a[2]), "r"(a[3]), "r"(b[0]), "r"(b[1]));
}
__device__ __forceinline__ float ex2f(float x) {
    float r;
    asm("ex2.approx.ftz.f32 %0, %1;" : "=f"(r) : "f"(x));
    return r;
}
__device__ __forceinline__ uint32_t packh2(float a, float b) {
    __half2 t = __floats2half2_rn(a, b);
    return *(uint32_t*)&t;
}
__device__ __forceinline__ void cp16(uint32_t smem, const void* g) {
    asm volatile("cp.async.cg.shared.global [%0], [%1], 16;"
                 :: "r"(smem), "l"(g) : "memory");
}
#define CP_COMMIT() asm volatile("cp.async.commit_group;" ::: "memory")
#define CP_WAIT0()  asm volatile("cp.async.wait_group 0;" ::: "memory")
#define CP_WAIT1()  asm volatile("cp.async.wait_group 1;" ::: "memory")

// ---------------------------------------------------------------------------
// fp32 -> fp16 cast, 4 tensors in one launch
// ---------------------------------------------------------------------------
__device__ __forceinline__ void cast4_do(const float4* src, uint2* hi, int i)
{
    float4 v = src[i];
    hi[i] = make_uint2(packh2(v.x, v.y), packh2(v.z, v.w));
}

__global__ __launch_bounds__(256)
void cast4_kernel(const float4* s0, uint2* h0, int n0,
                  const float4* s1, uint2* h1, int n1,
                  const float4* s2, uint2* h2, int n2,
                  const float4* s3, uint2* h3, int n3)
{
    int i = blockIdx.x * blockDim.x + threadIdx.x;
    if (i < n0) { cast4_do(s0, h0, i); return; }
    i -= n0;
    if (i < n1) { cast4_do(s1, h1, i); return; }
    i -= n1;
    if (i < n2) { cast4_do(s2, h2, i); return; }
    i -= n2;
    if (i < n3) { cast4_do(s3, h3, i); }
}

// ---------------------------------------------------------------------------
// HMMA GEMM (1-pass fp16): C = A*W^T + bias.  (r11 form, fp32 acc)
// CTA 128x128, BK=64, 256 threads (8 warps), 3-stage cp.async pipeline.
// ---------------------------------------------------------------------------
#define BM 128
#define BN 128
#define BKK 64
#define LDT 72                     // 144 B row (9 x 16B) -> LDSM conflict-free
#define GTILE (BM * LDT * 2)       // 18432 B per array
#define GST   (2 * GTILE)          // A + W per stage
#define GNIT  (KDIM / BKK)         // 16

__device__ __forceinline__ void gemm_core(
    const __half* __restrict__ A, const __half* __restrict__ W,
    const float* __restrict__ bias, float scale,
    float* __restrict__ Cf, __half* __restrict__ Ch)
{
    extern __shared__ char dsm[];
    __shared__ float s_bias[BN];

    const int tid = threadIdx.x;
    const int wid = tid >> 5;
    const int lid = tid & 31;
    const int wm  = wid & 1;
    const int wn  = wid >> 1;
    const int m0  = blockIdx.y * BM;
    const int n0  = blockIdx.x * BN;

    if (tid < BN) s_bias[tid] = bias[n0 + tid];

    const int lr     = lid & 7;
    const int half2_ = (lid >> 3) & 1;
    const int kh     = (lid >> 4) & 1;
    const int mbase  = wm * 64;
    const int nbase  = wn * 32;

    const uint32_t smem_base = smem_to_u32(dsm);

    float acc[4][4][4];
#pragma unroll
    for (int i = 0; i < 4; i++)
#pragma unroll
        for (int j = 0; j < 4; j++)
#pragma unroll
            for (int c = 0; c < 4; c++) acc[i][j][c] = 0.0f;

    auto load_stage = [&](int k0, int s) {
        uint32_t sb = smem_base + s * GST;
#pragma unroll
        for (int it = 0; it < 8; it++) {
            int e    = tid + it * 256;      // 0..2047
            int arr  = e >> 10;             // 0 A, 1 W
            int rem  = e & 1023;
            int row  = rem >> 3;
            int c    = rem & 7;
            const __half* g = (arr == 0)
                ? A + (size_t)(m0 + row) * KDIM + k0 + c * 8
                : W + (size_t)(n0 + row) * KDIM + k0 + c * 8;
            cp16(sb + arr * GTILE + row * (LDT * 2) + c * 16, g);
        }
        CP_COMMIT();
    };

    load_stage(0, 0);
    load_stage(BKK, 1);

    for (int i = 0; i < GNIT; i++) {
        if (i + 1 < GNIT) { CP_WAIT1(); } else { CP_WAIT0(); }
        __syncthreads();
        if (i + 2 < GNIT) load_stage((i + 2) * BKK, (i + 2) % 3);

        const uint32_t sb = smem_base + (i % 3) * GST;
        const uint32_t uA = sb;
        const uint32_t uW = sb + GTILE;

#pragma unroll
        for (int ks = 0; ks < 4; ks++) {
            const int kcol = ks * 16 + kh * 8;

            uint32_t af[4][4];
#pragma unroll
            for (int mt = 0; mt < 4; mt++) {
                int row = mbase + mt * 16 + lr + 8 * half2_;
                ldsm_x4(af[mt][0], af[mt][1], af[mt][2], af[mt][3],
                        uA + (uint32_t)(row * LDT + kcol) * 2);
            }
            uint32_t bf[4][2];
#pragma unroll
            for (int ntp = 0; ntp < 2; ntp++) {
                int row = nbase + ntp * 16 + lr + 8 * half2_;
                uint32_t r0, r1, r2, r3;
                ldsm_x4(r0, r1, r2, r3, uW + (uint32_t)(row * LDT + kcol) * 2);
                bf[ntp * 2 + 0][0] = r0; bf[ntp * 2 + 0][1] = r2;
                bf[ntp * 2 + 1][0] = r1; bf[ntp * 2 + 1][1] = r3;
            }
#pragma unroll
            for (int mt = 0; mt < 4; mt++)
#pragma unroll
                for (int nt = 0; nt < 4; nt++)
                    mma16816(acc[mt][nt], af[mt], bf[nt]);
        }
    }

    const int erow = lid >> 2;
    const int ecol = (lid & 3) * 2;
#pragma unroll
    for (int mt = 0; mt < 4; mt++) {
#pragma unroll
        for (int nt = 0; nt < 4; nt++) {
            int gm = m0 + mbase + mt * 16 + erow;
            int nc = nbase + nt * 8 + ecol;
            int gn = n0 + nc;
            float v0 = (acc[mt][nt][0] + s_bias[nc])     * scale;
            float v1 = (acc[mt][nt][1] + s_bias[nc + 1]) * scale;
            float v2 = (acc[mt][nt][2] + s_bias[nc])     * scale;
            float v3 = (acc[mt][nt][3] + s_bias[nc + 1]) * scale;
            if (Ch) {
                *(uint32_t*)&Ch[(size_t)gm * D_MODEL + gn]       = packh2(v0, v1);
                *(uint32_t*)&Ch[(size_t)(gm + 8) * D_MODEL + gn] = packh2(v2, v3);
            } else {
                *(float2*)&Cf[(size_t)gm * D_MODEL + gn]       = make_float2(v0, v1);
                *(float2*)&Cf[(size_t)(gm + 8) * D_MODEL + gn] = make_float2(v2, v3);
            }
        }
    }
}

__global__ __launch_bounds__(256, 1)
void qk_gemm_kernel(const float* __restrict__ bq, const float* __restrict__ bk)
{
    if (blockIdx.z == 0)
        gemm_core(g_Hh, g_Wqh, bq, QK_SCALE, nullptr, g_Qh);
    else
        gemm_core(g_Hh, g_Wkh, bk, 1.0f, nullptr, g_Kh);
}

__global__ __launch_bounds__(256, 1)
void out_gemm_kernel(const float* __restrict__ bo, float* __restrict__ out)
{
    gemm_core(g_AOh, g_Woh, bo, 1.0f, out, nullptr);
}

// ---------------------------------------------------------------------------
// HMMA flash attention (fp32 acc). 128-key smem stages, 2x64-key compute
// sub-tiles per stage, conditional (voted) rescale.
// grid (32 = B*NH, 16 = SEQ/128), 256 threads (8 warps), 128 q-rows per CTA.
// ---------------------------------------------------------------------------
#define SLDT 72                        // 144 B row
#define AARR (128 * SLDT * 2)          // 18432 B per array (K or V), 128 rows
#define AST  (2 * AARR)                // 36864 B per stage
#define NSTG (SEQ / 128)               // 16 stages

__global__ __launch_bounds__(256, 1)
void attn_mma_kernel()
{
    extern __shared__ char dsm[];
    __half* pool = (__half*)dsm;

    const int tid = threadIdx.x;
    const int wid = tid >> 5;
    const int lid = tid & 31;
    const int b   = blockIdx.x >> 4;
    const int h   = blockIdx.x & 15;
    const int q0  = blockIdx.y * 128;

    const int lr     = lid & 7;
    const int half2_ = (lid >> 3) & 1;
    const int kh     = (lid >> 4) & 1;

    const uint32_t smem_base = smem_to_u32(dsm);

    // ---- stage Q tile (128 x 64) through stage-0 area, extract frags ----
#pragma unroll
    for (int i = 0; i < 4; i++) {
        int e   = tid + i * 256;            // 0..1023
        int row = e >> 3;
        int c   = e & 7;
        const __half* src = g_Qh
            + (size_t)(b * SEQ + q0 + row) * D_MODEL + h * HDIM + c * 8;
        *(uint4*)(pool + row * SLDT + c * 8) = *(const uint4*)src;
    }
    __syncthreads();

    uint32_t qh[4][4];
    {
        const int wr = wid * 16;
#pragma unroll
        for (int kc = 0; kc < 4; kc++) {
            int row = wr + lr + 8 * half2_;
            int col = kc * 16 + kh * 8;
            ldsm_x4(qh[kc][0], qh[kc][1], qh[kc][2], qh[kc][3],
                    smem_base + (uint32_t)(row * SLDT + col) * 2);
        }
    }
    __syncthreads();

    float oacc[8][4];
#pragma unroll
    for (int nt = 0; nt < 8; nt++)
#pragma unroll
        for (int c = 0; c < 4; c++) oacc[nt][c] = 0.0f;
    float mx0 = -1e30f, mx1 = -1e30f, l0 = 0.0f, l1 = 0.0f;

    // stage = K rows [kb, kb+128) and V rows [kb, kb+128)
    auto load_stage = [&](int st, int s) {
        const int kb = st * 128;
        uint32_t sb = smem_base + s * AST;
#pragma unroll
        for (int i = 0; i < 8; i++) {
            int arr = i >> 2;                       // 0 K, 1 V
            int rem = ((i & 3) << 8) + tid;         // 0..1023
            int row = rem >> 3;                     // 0..127
            int c   = rem & 7;
            const __half* g = (arr == 0 ? g_Kh : g_Hh)
                + (size_t)(b * SEQ + kb + row) * D_MODEL + h * HDIM + c * 8;
            cp16(sb + arr * AARR + row * (SLDT * 2) + c * 16, g);
        }
        CP_COMMIT();
    };

    load_stage(0, 0);
    load_stage(1, 1);

    for (int st = 0; st < NSTG; st++) {
        if (st + 1 < NSTG) { CP_WAIT1(); } else { CP_WAIT0(); }
        __syncthreads();
        if (st + 2 < NSTG) load_stage(st + 2, (st + 2) % 3);

        const uint32_t sbs = smem_base + (st % 3) * AST;

#pragma unroll
        for (int sub = 0; sub < 2; sub++) {
            const uint32_t uK = sbs + (uint32_t)(sub * 64 * SLDT) * 2;
            const uint32_t uV = sbs + AARR + (uint32_t)(sub * 64 * SLDT) * 2;

            // ---- S = Q K^T ----
            float S[8][4];
#pragma unroll
            for (int nt = 0; nt < 8; nt++)
#pragma unroll
                for (int c = 0; c < 4; c++) S[nt][c] = 0.0f;

#pragma unroll
            for (int kc = 0; kc < 4; kc++) {
                uint32_t kb_[8][2];
#pragma unroll
                for (int ng = 0; ng < 4; ng++) {
                    int row = ng * 16 + lr + 8 * half2_;
                    int col = kc * 16 + kh * 8;
                    uint32_t r0, r1, r2, r3;
                    ldsm_x4(r0, r1, r2, r3, uK + (uint32_t)(row * SLDT + col) * 2);
                    kb_[ng * 2 + 0][0] = r0; kb_[ng * 2 + 0][1] = r2;
                    kb_[ng * 2 + 1][0] = r1; kb_[ng * 2 + 1][1] = r3;
                }
#pragma unroll
                for (int nt = 0; nt < 8; nt++)
                    mma16816(S[nt], qh[kc], kb_[nt]);
            }

            // ---- online softmax (voted conditional rescale) ----
            float tm0 = -1e30f, tm1 = -1e30f;
#pragma unroll
            for (int nt = 0; nt < 8; nt++) {
                tm0 = fmaxf(tm0, fmaxf(S[nt][0], S[nt][1]));
                tm1 = fmaxf(tm1, fmaxf(S[nt][2], S[nt][3]));
            }
            tm0 = fmaxf(tm0, __shfl_xor_sync(0xffffffffu, tm0, 1));
            tm0 = fmaxf(tm0, __shfl_xor_sync(0xffffffffu, tm0, 2));
            tm1 = fmaxf(tm1, __shfl_xor_sync(0xffffffffu, tm1, 1));
            tm1 = fmaxf(tm1, __shfl_xor_sync(0xffffffffu, tm1, 2));

            bool grew = (tm0 > mx0) || (tm1 > mx1);
            if (__any_sync(0xffffffffu, grew)) {
                float mn0 = fmaxf(mx0, tm0), mn1 = fmaxf(mx1, tm1);
                float a0 = ex2f(mx0 - mn0), a1 = ex2f(mx1 - mn1);
                l0 *= a0; l1 *= a1;
#pragma unroll
                for (int nt = 0; nt < 8; nt++) {
                    oacc[nt][0] *= a0; oacc[nt][1] *= a0;
                    oacc[nt][2] *= a1; oacc[nt][3] *= a1;
                }
                mx0 = mn0; mx1 = mn1;
            }

            uint32_t pa[4][4];
            float rs0 = 0.0f, rs1 = 0.0f;
#pragma unroll
            for (int j = 0; j < 4; j++) {
#pragma unroll
                for (int sg = 0; sg < 2; sg++) {
                    int t2 = j * 2 + sg;
                    float p0 = ex2f(S[t2][0] - mx0);
                    float p1 = ex2f(S[t2][1] - mx0);
                    float p2 = ex2f(S[t2][2] - mx1);
                    float p3 = ex2f(S[t2][3] - mx1);
                    rs0 += p0 + p1;
                    rs1 += p2 + p3;
                    pa[j][sg * 2 + 0] = packh2(p0, p1);
                    pa[j][sg * 2 + 1] = packh2(p2, p3);
                }
            }
            rs0 += __shfl_xor_sync(0xffffffffu, rs0, 1);
            rs0 += __shfl_xor_sync(0xffffffffu, rs0, 2);
            rs1 += __shfl_xor_sync(0xffffffffu, rs1, 1);
            rs1 += __shfl_xor_sync(0xffffffffu, rs1, 2);
            l0 += rs0;
            l1 += rs1;

            // ---- O += P V ----
#pragma unroll
            for (int kc = 0; kc < 4; kc++) {
                uint32_t vb[8][2];
#pragma unroll
                for (int dg = 0; dg < 4; dg++) {
                    int rowk = kc * 16 + lr + 8 * half2_;
                    int dimc = dg * 16 + kh * 8;
                    uint32_t r0, r1, r2, r3;
                    ldsm_x4_t(r0, r1, r2, r3, uV + (uint32_t)(rowk * SLDT + dimc) * 2);
                    vb[dg * 2 + 0][0] = r0; vb[dg * 2 + 0][1] = r1;
                    vb[dg * 2 + 1][0] = r2; vb[dg * 2 + 1][1] = r3;
                }
#pragma unroll
                for (int nt = 0; nt < 8; nt++)
                    mma16816(oacc[nt], pa[kc], vb[nt]);
            }
        }
    }

    // ---- epilogue ----
    const float inv0 = 1.0f / l0;
    const float inv1 = 1.0f / l1;
    const int gr  = b * SEQ + q0 + wid * 16 + (lid >> 2);
    const int col = h * HDIM + (lid & 3) * 2;
#pragma unroll
    for (int nt = 0; nt < 8; nt++) {
        int gc = col + nt * 8;
        float v0 = oacc[nt][0] * inv0, v1 = oacc[nt][1] * inv0;
        float v2 = oacc[nt][2] * inv1, v3 = oacc[nt][3] * inv1;
        *(uint32_t*)&g_AOh[(size_t)gr * D_MODEL + gc]       = packh2(v0, v1);
        *(uint32_t*)&g_AOh[(size_t)(gr + 8) * D_MODEL + gc] = packh2(v2, v3);
    }
}

// ---------------------------------------------------------------------------
extern "C" void kernel_launch(void* const* d_in, const int* in_sizes, int n_in,
                              void* d_out, int out_size)
{
    (void)in_sizes; (void)n_in; (void)out_size;
    const float* H  = (const float*)d_in[0];
    const float* Wq = (const float*)d_in[1];
    const float* bq = (const float*)d_in[2];
    const float* Wk = (const float*)d_in[3];
    const float* bk = (const float*)d_in[4];
    const float* Wo = (const float*)d_in[5];
    const float* bo = (const float*)d_in[6];
    float* out = (float*)d_out;

    void *p_Hh, *p_Wqh, *p_Wkh, *p_Woh;
    cudaGetSymbolAddress(&p_Hh,  g_Hh);
    cudaGetSymbolAddress(&p_Wqh, g_Wqh);
    cudaGetSymbolAddress(&p_Wkh, g_Wkh);
    cudaGetSymbolAddress(&p_Woh, g_Woh);

    const int GSMEM = 3 * GST;    // 110,592 B
    const int ASMEM = 3 * AST;    // 110,592 B

    cudaFuncSetAttribute(qk_gemm_kernel,
                         cudaFuncAttributeMaxDynamicSharedMemorySize, GSMEM);
    cudaFuncSetAttribute(out_gemm_kernel,
                         cudaFuncAttributeMaxDynamicSharedMemorySize, GSMEM);
    cudaFuncSetAttribute(attn_mma_kernel,
                         cudaFuncAttributeMaxDynamicSharedMemorySize, ASMEM);

    const int nH4 = NROWS * D_MODEL / 4;      // 1,048,576
    const int nW4 = D_MODEL * D_MODEL / 4;    // 262,144
    const int nTot = nH4 + 3 * nW4;           // 1,835,008

    cast4_kernel<<<(nTot + 255) / 256, 256>>>(
        (const float4*)H,  (uint2*)p_Hh,  nH4,
        (const float4*)Wq, (uint2*)p_Wqh, nW4,
        (const float4*)Wk, (uint2*)p_Wkh, nW4,
        (const float4*)Wo, (uint2*)p_Woh, nW4);

    dim3 ggrid(D_MODEL / BN, NROWS / BM, 2);   // (8, 32, 2)
    qk_gemm_kernel<<<ggrid, 256, GSMEM>>>(bq, bk);

    dim3 agrid(BATCH * NHEADS, SEQ / 128);     // (32, 16)
    attn_mma_kernel<<<agrid, 256, ASMEM>>>();

    dim3 ogrid(D_MODEL / BN, NROWS / BM, 1);   // (8, 32)
    out_gemm_kernel<<<ogrid, 256, GSMEM>>>(bo, out);
}

// round 14
// speedup vs baseline: 1.0653x; 1.0157x over previous
#include <cuda_runtime.h>
#include <cuda_fp16.h>
#include <cstdint>

#define D_MODEL 1024
#define NHEADS  16
#define HDIM    64
#define BATCH   2
#define SEQ     2048
#define NROWS   (BATCH * SEQ)     // 4096
#define KDIM    D_MODEL

// softmax scale folded into Q projection: 1/sqrt(64) * log2(e)
#define QK_SCALE 0.1803368801111244f

// ---------------------------------------------------------------------------
// Scratch (device globals)
// ---------------------------------------------------------------------------
__device__ __half g_Hh [NROWS * D_MODEL];   // H, also V in attention
__device__ __half g_Qh [NROWS * D_MODEL];
__device__ __half g_Kh [NROWS * D_MODEL];
__device__ __half g_AOh[NROWS * D_MODEL];
__device__ __half g_Wqh[D_MODEL * D_MODEL];
__device__ __half g_Wkh[D_MODEL * D_MODEL];
__device__ __half g_Woh[D_MODEL * D_MODEL];

// ---------------------------------------------------------------------------
// helpers
// ---------------------------------------------------------------------------
__device__ __forceinline__ uint32_t smem_to_u32(const void* p) {
    uint32_t a;
    asm("{ .reg .u64 t; cvta.to.shared.u64 t, %1; cvt.u32.u64 %0, t; }"
        : "=r"(a) : "l"(p));
    return a;
}
__device__ __forceinline__ void ldsm_x4(uint32_t& r0, uint32_t& r1,
                                        uint32_t& r2, uint32_t& r3, uint32_t addr) {
    asm volatile("ldmatrix.sync.aligned.m8n8.x4.shared.b16 {%0,%1,%2,%3}, [%4];"
                 : "=r"(r0), "=r"(r1), "=r"(r2), "=r"(r3) : "r"(addr));
}
__device__ __forceinline__ void ldsm_x4_t(uint32_t& r0, uint32_t& r1,
                                          uint32_t& r2, uint32_t& r3, uint32_t addr) {
    asm volatile("ldmatrix.sync.aligned.m8n8.x4.trans.shared.b16 {%0,%1,%2,%3}, [%4];"
                 : "=r"(r0), "=r"(r1), "=r"(r2), "=r"(r3) : "r"(addr));
}
__device__ __forceinline__ void mma16816(float* c, const uint32_t* a,
                                         const uint32_t* b) {
    asm volatile(
        "mma.sync.aligned.m16n8k16.row.col.f32.f16.f16.f32 "
        "{%0,%1,%2,%3}, {%4,%5,%6,%7}, {%8,%9}, {%0,%1,%2,%3};"
        : "+f"(c[0]), "+f"(c[1]), "+f"(c[2]), "+f"(c[3])
        : "r"(a[0]), "r"(a[1]), "r"(a[2]), "r"(a[3]), "r"(b[0]), "r"(b[1]));
}
__device__ __forceinline__ float ex2f(float x) {
    float r;
    asm("ex2.approx.ftz.f32 %0, %1;" : "=f"(r) : "f"(x));
    return r;
}
__device__ __forceinline__ uint32_t h2exp2u(uint32_t x) {
    uint32_t r;
    asm("ex2.approx.f16x2 %0, %1;" : "=r"(r) : "r"(x));
    return r;
}
__device__ __forceinline__ uint32_t packh2(float a, float b) {
    __half2 t = __floats2half2_rn(a, b);
    return *(uint32_t*)&t;
}
__device__ __forceinline__ void cp16(uint32_t smem, const void* g) {
    asm volatile("cp.async.cg.shared.global [%0], [%1], 16;"
                 :: "r"(smem), "l"(g) : "memory");
}
#define CP_COMMIT() asm volatile("cp.async.commit_group;" ::: "memory")
#define CP_WAIT0()  asm volatile("cp.async.wait_group 0;" ::: "memory")
#define CP_WAIT1()  asm volatile("cp.async.wait_group 1;" ::: "memory")

// ---------------------------------------------------------------------------
// fp32 -> fp16 cast, 4 tensors in one launch
// ---------------------------------------------------------------------------
__device__ __forceinline__ void cast4_do(const float4* src, uint2* hi, int i)
{
    float4 v = src[i];
    hi[i] = make_uint2(packh2(v.x, v.y), packh2(v.z, v.w));
}

__global__ __launch_bounds__(256)
void cast4_kernel(const float4* s0, uint2* h0, int n0,
                  const float4* s1, uint2* h1, int n1,
                  const float4* s2, uint2* h2, int n2,
                  const float4* s3, uint2* h3, int n3)
{
    int i = blockIdx.x * blockDim.x + threadIdx.x;
    if (i < n0) { cast4_do(s0, h0, i); return; }
    i -= n0;
    if (i < n1) { cast4_do(s1, h1, i); return; }
    i -= n1;
    if (i < n2) { cast4_do(s2, h2, i); return; }
    i -= n2;
    if (i < n3) { cast4_do(s3, h3, i); }
}

// ---------------------------------------------------------------------------
// HMMA GEMM (1-pass fp16): C = A*W^T + bias.
// CTA 128x128, BK=64, 256 threads (8 warps), 3-stage cp.async pipeline.
// ---------------------------------------------------------------------------
#define BM 128
#define BN 128
#define BKK 64
#define LDT 72                     // 144 B row (9 x 16B) -> LDSM conflict-free
#define GTILE (BM * LDT * 2)       // 18432 B per array
#define GST   (2 * GTILE)          // A + W per stage
#define GNIT  (KDIM / BKK)         // 16

__device__ __forceinline__ void gemm_core(
    const __half* __restrict__ A, const __half* __restrict__ W,
    const float* __restrict__ bias, float scale,
    float* __restrict__ Cf, __half* __restrict__ Ch)
{
    extern __shared__ char dsm[];
    __shared__ float s_bias[BN];

    const int tid = threadIdx.x;
    const int wid = tid >> 5;
    const int lid = tid & 31;
    const int wm  = wid & 1;
    const int wn  = wid >> 1;
    const int m0  = blockIdx.y * BM;
    const int n0  = blockIdx.x * BN;

    if (tid < BN) s_bias[tid] = bias[n0 + tid];

    const int lr     = lid & 7;
    const int half2_ = (lid >> 3) & 1;
    const int kh     = (lid >> 4) & 1;
    const int mbase  = wm * 64;
    const int nbase  = wn * 32;

    const uint32_t smem_base = smem_to_u32(dsm);

    float acc[4][4][4];
#pragma unroll
    for (int i = 0; i < 4; i++)
#pragma unroll
        for (int j = 0; j < 4; j++)
#pragma unroll
            for (int c = 0; c < 4; c++) acc[i][j][c] = 0.0f;

    auto load_stage = [&](int k0, int s) {
        uint32_t sb = smem_base + s * GST;
#pragma unroll
        for (int it = 0; it < 8; it++) {
            int e    = tid + it * 256;      // 0..2047
            int arr  = e >> 10;             // 0 A, 1 W
            int rem  = e & 1023;
            int row  = rem >> 3;
            int c    = rem & 7;
            const __half* g = (arr == 0)
                ? A + (size_t)(m0 + row) * KDIM + k0 + c * 8
                : W + (size_t)(n0 + row) * KDIM + k0 + c * 8;
            cp16(sb + arr * GTILE + row * (LDT * 2) + c * 16, g);
        }
        CP_COMMIT();
    };

    load_stage(0, 0);
    load_stage(BKK, 1);

    for (int i = 0; i < GNIT; i++) {
        if (i + 1 < GNIT) { CP_WAIT1(); } else { CP_WAIT0(); }
        __syncthreads();
        if (i + 2 < GNIT) load_stage((i + 2) * BKK, (i + 2) % 3);

        const uint32_t sb = smem_base + (i % 3) * GST;
        const uint32_t uA = sb;
        const uint32_t uW = sb + GTILE;

#pragma unroll
        for (int ks = 0; ks < 4; ks++) {
            const int kcol = ks * 16 + kh * 8;

            uint32_t af[4][4];
#pragma unroll
            for (int mt = 0; mt < 4; mt++) {
                int row = mbase + mt * 16 + lr + 8 * half2_;
                ldsm_x4(af[mt][0], af[mt][1], af[mt][2], af[mt][3],
                        uA + (uint32_t)(row * LDT + kcol) * 2);
            }
            uint32_t bf[4][2];
#pragma unroll
            for (int ntp = 0; ntp < 2; ntp++) {
                int row = nbase + ntp * 16 + lr + 8 * half2_;
                uint32_t r0, r1, r2, r3;
                ldsm_x4(r0, r1, r2, r3, uW + (uint32_t)(row * LDT + kcol) * 2);
                bf[ntp * 2 + 0][0] = r0; bf[ntp * 2 + 0][1] = r2;
                bf[ntp * 2 + 1][0] = r1; bf[ntp * 2 + 1][1] = r3;
            }
#pragma unroll
            for (int mt = 0; mt < 4; mt++)
#pragma unroll
                for (int nt = 0; nt < 4; nt++)
                    mma16816(acc[mt][nt], af[mt], bf[nt]);
        }
    }

    const int erow = lid >> 2;
    const int ecol = (lid & 3) * 2;
#pragma unroll
    for (int mt = 0; mt < 4; mt++) {
#pragma unroll
        for (int nt = 0; nt < 4; nt++) {
            int gm = m0 + mbase + mt * 16 + erow;
            int nc = nbase + nt * 8 + ecol;
            int gn = n0 + nc;
            float v0 = (acc[mt][nt][0] + s_bias[nc])     * scale;
            float v1 = (acc[mt][nt][1] + s_bias[nc + 1]) * scale;
            float v2 = (acc[mt][nt][2] + s_bias[nc])     * scale;
            float v3 = (acc[mt][nt][3] + s_bias[nc + 1]) * scale;
            if (Ch) {
                *(uint32_t*)&Ch[(size_t)gm * D_MODEL + gn]       = packh2(v0, v1);
                *(uint32_t*)&Ch[(size_t)(gm + 8) * D_MODEL + gn] = packh2(v2, v3);
            } else {
                *(float2*)&Cf[(size_t)gm * D_MODEL + gn]       = make_float2(v0, v1);
                *(float2*)&Cf[(size_t)(gm + 8) * D_MODEL + gn] = make_float2(v2, v3);
            }
        }
    }
}

__global__ __launch_bounds__(256, 1)
void qk_gemm_kernel(const float* __restrict__ bq, const float* __restrict__ bk)
{
    if (blockIdx.z == 0)
        gemm_core(g_Hh, g_Wqh, bq, QK_SCALE, nullptr, g_Qh);
    else
        gemm_core(g_Hh, g_Wkh, bk, 1.0f, nullptr, g_Kh);
}

__global__ __launch_bounds__(256, 1)
void out_gemm_kernel(const float* __restrict__ bo, float* __restrict__ out)
{
    gemm_core(g_AOh, g_Woh, bo, 1.0f, out, nullptr);
}

// ---------------------------------------------------------------------------
// HMMA flash attention (fp32 acc). 128-key stages, 2x64 sub-tiles, voted
// rescale, f16x2 exp, row-sum l via ones-MMA.
// grid (32 = B*NH, 16 = SEQ/128), 256 threads (8 warps), 128 q-rows per CTA.
// ---------------------------------------------------------------------------
#define SLDT 72                        // 144 B row
#define AARR (128 * SLDT * 2)          // 18432 B per array (K or V)
#define AST  (2 * AARR)                // 36864 B per stage
#define NSTG (SEQ / 128)               // 16 stages

__global__ __launch_bounds__(256, 1)
void attn_mma_kernel()
{
    extern __shared__ char dsm[];
    __half* pool = (__half*)dsm;

    const int tid = threadIdx.x;
    const int wid = tid >> 5;
    const int lid = tid & 31;
    const int b   = blockIdx.x >> 4;
    const int h   = blockIdx.x & 15;
    const int q0  = blockIdx.y * 128;

    const int lr     = lid & 7;
    const int half2_ = (lid >> 3) & 1;
    const int kh     = (lid >> 4) & 1;

    const uint32_t smem_base = smem_to_u32(dsm);

    // ---- stage Q tile (128 x 64) through stage-0 area, extract frags ----
#pragma unroll
    for (int i = 0; i < 4; i++) {
        int e   = tid + i * 256;            // 0..1023
        int row = e >> 3;
        int c   = e & 7;
        const __half* src = g_Qh
            + (size_t)(b * SEQ + q0 + row) * D_MODEL + h * HDIM + c * 8;
        *(uint4*)(pool + row * SLDT + c * 8) = *(const uint4*)src;
    }
    __syncthreads();

    uint32_t qh[4][4];
    {
        const int wr = wid * 16;
#pragma unroll
        for (int kc = 0; kc < 4; kc++) {
            int row = wr + lr + 8 * half2_;
            int col = kc * 16 + kh * 8;
            ldsm_x4(qh[kc][0], qh[kc][1], qh[kc][2], qh[kc][3],
                    smem_base + (uint32_t)(row * SLDT + col) * 2);
        }
    }
    __syncthreads();

    float oacc[8][4];
#pragma unroll
    for (int nt = 0; nt < 8; nt++)
#pragma unroll
        for (int c = 0; c < 4; c++) oacc[nt][c] = 0.0f;
    float lacc[4] = {0.0f, 0.0f, 0.0f, 0.0f};   // l via ones-MMA: [0]=row r, [2]=row r+8
    float mx0 = -1e30f, mx1 = -1e30f;

    const uint32_t ones2[2] = {0x3C003C00u, 0x3C003C00u};

    auto load_stage = [&](int st, int s) {
        const int kb = st * 128;
        uint32_t sb = smem_base + s * AST;
#pragma unroll
        for (int i = 0; i < 8; i++) {
            int arr = i >> 2;                       // 0 K, 1 V
            int rem = ((i & 3) << 8) + tid;         // 0..1023
            int row = rem >> 3;                     // 0..127
            int c   = rem & 7;
            const __half* g = (arr == 0 ? g_Kh : g_Hh)
                + (size_t)(b * SEQ + kb + row) * D_MODEL + h * HDIM + c * 8;
            cp16(sb + arr * AARR + row * (SLDT * 2) + c * 16, g);
        }
        CP_COMMIT();
    };

    load_stage(0, 0);
    load_stage(1, 1);

    for (int st = 0; st < NSTG; st++) {
        if (st + 1 < NSTG) { CP_WAIT1(); } else { CP_WAIT0(); }
        __syncthreads();
        if (st + 2 < NSTG) load_stage(st + 2, (st + 2) % 3);

        const uint32_t sbs = smem_base + (st % 3) * AST;

#pragma unroll
        for (int sub = 0; sub < 2; sub++) {
            const uint32_t uK = sbs + (uint32_t)(sub * 64 * SLDT) * 2;
            const uint32_t uV = sbs + AARR + (uint32_t)(sub * 64 * SLDT) * 2;

            // ---- S = Q K^T ----
            float S[8][4];
#pragma unroll
            for (int nt = 0; nt < 8; nt++)
#pragma unroll
                for (int c = 0; c < 4; c++) S[nt][c] = 0.0f;

#pragma unroll
            for (int kc = 0; kc < 4; kc++) {
                uint32_t kb_[8][2];
#pragma unroll
                for (int ng = 0; ng < 4; ng++) {
                    int row = ng * 16 + lr + 8 * half2_;
                    int col = kc * 16 + kh * 8;
                    uint32_t r0, r1, r2, r3;
                    ldsm_x4(r0, r1, r2, r3, uK + (uint32_t)(row * SLDT + col) * 2);
                    kb_[ng * 2 + 0][0] = r0; kb_[ng * 2 + 0][1] = r2;
                    kb_[ng * 2 + 1][0] = r1; kb_[ng * 2 + 1][1] = r3;
                }
#pragma unroll
                for (int nt = 0; nt < 8; nt++)
                    mma16816(S[nt], qh[kc], kb_[nt]);
            }

            // ---- online softmax (voted conditional rescale) ----
            float tm0 = -1e30f, tm1 = -1e30f;
#pragma unroll
            for (int nt = 0; nt < 8; nt++) {
                tm0 = fmaxf(tm0, fmaxf(S[nt][0], S[nt][1]));
                tm1 = fmaxf(tm1, fmaxf(S[nt][2], S[nt][3]));
            }
            tm0 = fmaxf(tm0, __shfl_xor_sync(0xffffffffu, tm0, 1));
            tm0 = fmaxf(tm0, __shfl_xor_sync(0xffffffffu, tm0, 2));
            tm1 = fmaxf(tm1, __shfl_xor_sync(0xffffffffu, tm1, 1));
            tm1 = fmaxf(tm1, __shfl_xor_sync(0xffffffffu, tm1, 2));

            bool grew = (tm0 > mx0) || (tm1 > mx1);
            if (__any_sync(0xffffffffu, grew)) {
                float mn0 = fmaxf(mx0, tm0), mn1 = fmaxf(mx1, tm1);
                float a0 = ex2f(mx0 - mn0), a1 = ex2f(mx1 - mn1);
                lacc[0] *= a0; lacc[1] *= a0;
                lacc[2] *= a1; lacc[3] *= a1;
#pragma unroll
                for (int nt = 0; nt < 8; nt++) {
                    oacc[nt][0] *= a0; oacc[nt][1] *= a0;
                    oacc[nt][2] *= a1; oacc[nt][3] *= a1;
                }
                mx0 = mn0; mx1 = mn1;
            }

            // ---- P = exp2(S - mx) via f16x2 MUFU ----
            uint32_t pa[4][4];
#pragma unroll
            for (int j = 0; j < 4; j++) {
#pragma unroll
                for (int sg = 0; sg < 2; sg++) {
                    int t2 = j * 2 + sg;
                    pa[j][sg * 2 + 0] = h2exp2u(packh2(S[t2][0] - mx0, S[t2][1] - mx0));
                    pa[j][sg * 2 + 1] = h2exp2u(packh2(S[t2][2] - mx1, S[t2][3] - mx1));
                }
            }

            // ---- O += P V ; l += P 1 (ones-MMA folded into kc loop) ----
#pragma unroll
            for (int kc = 0; kc < 4; kc++) {
                uint32_t vb[8][2];
#pragma unroll
                for (int dg = 0; dg < 4; dg++) {
                    int rowk = kc * 16 + lr + 8 * half2_;
                    int dimc = dg * 16 + kh * 8;
                    uint32_t r0, r1, r2, r3;
                    ldsm_x4_t(r0, r1, r2, r3, uV + (uint32_t)(rowk * SLDT + dimc) * 2);
                    vb[dg * 2 + 0][0] = r0; vb[dg * 2 + 0][1] = r1;
                    vb[dg * 2 + 1][0] = r2; vb[dg * 2 + 1][1] = r3;
                }
                mma16816(lacc, pa[kc], ones2);
#pragma unroll
                for (int nt = 0; nt < 8; nt++)
                    mma16816(oacc[nt], pa[kc], vb[nt]);
            }
        }
    }

    // ---- epilogue ----
    const float inv0 = 1.0f / lacc[0];
    const float inv1 = 1.0f / lacc[2];
    const int gr  = b * SEQ + q0 + wid * 16 + (lid >> 2);
    const int col = h * HDIM + (lid & 3) * 2;
#pragma unroll
    for (int nt = 0; nt < 8; nt++) {
        int gc = col + nt * 8;
        float v0 = oacc[nt][0] * inv0, v1 = oacc[nt][1] * inv0;
        float v2 = oacc[nt][2] * inv1, v3 = oacc[nt][3] * inv1;
        *(uint32_t*)&g_AOh[(size_t)gr * D_MODEL + gc]       = packh2(v0, v1);
        *(uint32_t*)&g_AOh[(size_t)(gr + 8) * D_MODEL + gc] = packh2(v2, v3);
    }
}

// ---------------------------------------------------------------------------
extern "C" void kernel_launch(void* const* d_in, const int* in_sizes, int n_in,
                              void* d_out, int out_size)
{
    (void)in_sizes; (void)n_in; (void)out_size;
    const float* H  = (const float*)d_in[0];
    const float* Wq = (const float*)d_in[1];
    const float* bq = (const float*)d_in[2];
    const float* Wk = (const float*)d_in[3];
    const float* bk = (const float*)d_in[4];
    const float* Wo = (const float*)d_in[5];
    const float* bo = (const float*)d_in[6];
    float* out = (float*)d_out;

    void *p_Hh, *p_Wqh, *p_Wkh, *p_Woh;
    cudaGetSymbolAddress(&p_Hh,  g_Hh);
    cudaGetSymbolAddress(&p_Wqh, g_Wqh);
    cudaGetSymbolAddress(&p_Wkh, g_Wkh);
    cudaGetSymbolAddress(&p_Woh, g_Woh);

    const int GSMEM = 3 * GST;    // 110,592 B
    const int ASMEM = 3 * AST;    // 110,592 B

    cudaFuncSetAttribute(qk_gemm_kernel,
                         cudaFuncAttributeMaxDynamicSharedMemorySize, GSMEM);
    cudaFuncSetAttribute(out_gemm_kernel,
                         cudaFuncAttributeMaxDynamicSharedMemorySize, GSMEM);
    cudaFuncSetAttribute(attn_mma_kernel,
                         cudaFuncAttributeMaxDynamicSharedMemorySize, ASMEM);

    const int nH4 = NROWS * D_MODEL / 4;      // 1,048,576
    const int nW4 = D_MODEL * D_MODEL / 4;    // 262,144
    const int nTot = nH4 + 3 * nW4;           // 1,835,008

    cast4_kernel<<<(nTot + 255) / 256, 256>>>(
        (const float4*)H,  (uint2*)p_Hh,  nH4,
        (const float4*)Wq, (uint2*)p_Wqh, nW4,
        (const float4*)Wk, (uint2*)p_Wkh, nW4,
        (const float4*)Wo, (uint2*)p_Woh, nW4);

    dim3 ggrid(D_MODEL / BN, NROWS / BM, 2);   // (8, 32, 2)
    qk_gemm_kernel<<<ggrid, 256, GSMEM>>>(bq, bk);

    dim3 agrid(BATCH * NHEADS, SEQ / 128);     // (32, 16)
    attn_mma_kernel<<<agrid, 256, ASMEM>>>();

    dim3 ogrid(D_MODEL / BN, NROWS / BM, 1);   // (8, 32)
    out_gemm_kernel<<<ogrid, 256, GSMEM>>>(bo, out);
}

// round 15
// speedup vs baseline: 1.0664x; 1.0010x over previous
#include <cuda_runtime.h>
#include <cuda_fp16.h>
#include <cstdint>

#define D_MODEL 1024
#define NHEADS  16
#define HDIM    64
#define BATCH   2
#define SEQ     2048
#define NROWS   (BATCH * SEQ)     // 4096
#define KDIM    D_MODEL

// softmax scale folded into Q projection: 1/sqrt(64) * log2(e)
#define QK_SCALE 0.1803368801111244f

// ---------------------------------------------------------------------------
// Scratch (device globals)
// ---------------------------------------------------------------------------
__device__ __half g_Hh [NROWS * D_MODEL];   // H, also V in attention
__device__ __half g_Qh [NROWS * D_MODEL];
__device__ __half g_Kh [NROWS * D_MODEL];
__device__ __half g_AOh[NROWS * D_MODEL];
__device__ __half g_Wqh[D_MODEL * D_MODEL];
__device__ __half g_Wkh[D_MODEL * D_MODEL];
__device__ __half g_Woh[D_MODEL * D_MODEL];

// ---------------------------------------------------------------------------
// helpers
// ---------------------------------------------------------------------------
__device__ __forceinline__ uint32_t smem_to_u32(const void* p) {
    uint32_t a;
    asm("{ .reg .u64 t; cvta.to.shared.u64 t, %1; cvt.u32.u64 %0, t; }"
        : "=r"(a) : "l"(p));
    return a;
}
__device__ __forceinline__ void ldsm_x4(uint32_t& r0, uint32_t& r1,
                                        uint32_t& r2, uint32_t& r3, uint32_t addr) {
    asm volatile("ldmatrix.sync.aligned.m8n8.x4.shared.b16 {%0,%1,%2,%3}, [%4];"
                 : "=r"(r0), "=r"(r1), "=r"(r2), "=r"(r3) : "r"(addr));
}
__device__ __forceinline__ void ldsm_x4_t(uint32_t& r0, uint32_t& r1,
                                          uint32_t& r2, uint32_t& r3, uint32_t addr) {
    asm volatile("ldmatrix.sync.aligned.m8n8.x4.trans.shared.b16 {%0,%1,%2,%3}, [%4];"
                 : "=r"(r0), "=r"(r1), "=r"(r2), "=r"(r3) : "r"(addr));
}
__device__ __forceinline__ void mma16816(float* c, const uint32_t* a,
                                         const uint32_t* b) {
    asm volatile(
        "mma.sync.aligned.m16n8k16.row.col.f32.f16.f16.f32 "
        "{%0,%1,%2,%3}, {%4,%5,%6,%7}, {%8,%9}, {%0,%1,%2,%3};"
        : "+f"(c[0]), "+f"(c[1]), "+f"(c[2]), "+f"(c[3])
        : "r"(a[0]), "r"(a[1]), "r"(a[2]), "r"(a[3]), "r"(b[0]), "r"(b[1]));
}
__device__ __forceinline__ float ex2f(float x) {
    float r;
    asm("ex2.approx.ftz.f32 %0, %1;" : "=f"(r) : "f"(x));
    return r;
}
__device__ __forceinline__ uint32_t h2exp2u(uint32_t x) {
    uint32_t r;
    asm("ex2.approx.f16x2 %0, %1;" : "=r"(r) : "r"(x));
    return r;
}
__device__ __forceinline__ uint32_t packh2(float a, float b) {
    __half2 t = __floats2half2_rn(a, b);
    return *(uint32_t*)&t;
}
__device__ __forceinline__ void cp16(uint32_t smem, const void* g) {
    asm volatile("cp.async.cg.shared.global [%0], [%1], 16;"
                 :: "r"(smem), "l"(g) : "memory");
}
#define CP_COMMIT() asm volatile("cp.async.commit_group;" ::: "memory")
#define CP_WAIT0()  asm volatile("cp.async.wait_group 0;" ::: "memory")
#define CP_WAIT1()  asm volatile("cp.async.wait_group 1;" ::: "memory")

// ---------------------------------------------------------------------------
// fp32 -> fp16 cast, 4 tensors in one launch
// ---------------------------------------------------------------------------
__device__ __forceinline__ void cast4_do(const float4* src, uint2* hi, int i)
{
    float4 v = src[i];
    hi[i] = make_uint2(packh2(v.x, v.y), packh2(v.z, v.w));
}

__global__ __launch_bounds__(256)
void cast4_kernel(const float4* s0, uint2* h0, int n0,
                  const float4* s1, uint2* h1, int n1,
                  const float4* s2, uint2* h2, int n2,
                  const float4* s3, uint2* h3, int n3)
{
    int i = blockIdx.x * blockDim.x + threadIdx.x;
    if (i < n0) { cast4_do(s0, h0, i); return; }
    i -= n0;
    if (i < n1) { cast4_do(s1, h1, i); return; }
    i -= n1;
    if (i < n2) { cast4_do(s2, h2, i); return; }
    i -= n2;
    if (i < n3) { cast4_do(s3, h3, i); }
}

// ---------------------------------------------------------------------------
// HMMA GEMM (1-pass fp16): C = A*W^T + bias.
// CTA 128x128, BK=64, 256 threads (8 warps), 2-stage cp.async pipeline,
// 2 CTAs/SM (smem 73.7 KB, regs <=128).
// ---------------------------------------------------------------------------
#define BM 128
#define BN 128
#define BKK 64
#define LDT 72                     // 144 B row (9 x 16B) -> LDSM conflict-free
#define GTILE (BM * LDT * 2)       // 18432 B per array
#define GST   (2 * GTILE)          // A + W per stage
#define GNIT  (KDIM / BKK)         // 16

__device__ __forceinline__ void gemm_core(
    const __half* __restrict__ A, const __half* __restrict__ W,
    const float* __restrict__ bias, float scale,
    float* __restrict__ Cf, __half* __restrict__ Ch)
{
    extern __shared__ char dsm[];
    __shared__ float s_bias[BN];

    const int tid = threadIdx.x;
    const int wid = tid >> 5;
    const int lid = tid & 31;
    const int wm  = wid & 1;
    const int wn  = wid >> 1;
    const int m0  = blockIdx.y * BM;
    const int n0  = blockIdx.x * BN;

    if (tid < BN) s_bias[tid] = bias[n0 + tid];

    const int lr     = lid & 7;
    const int half2_ = (lid >> 3) & 1;
    const int kh     = (lid >> 4) & 1;
    const int mbase  = wm * 64;
    const int nbase  = wn * 32;

    const uint32_t smem_base = smem_to_u32(dsm);

    float acc[4][4][4];
#pragma unroll
    for (int i = 0; i < 4; i++)
#pragma unroll
        for (int j = 0; j < 4; j++)
#pragma unroll
            for (int c = 0; c < 4; c++) acc[i][j][c] = 0.0f;

    auto load_stage = [&](int k0, int s) {
        uint32_t sb = smem_base + s * GST;
#pragma unroll
        for (int it = 0; it < 8; it++) {
            int e    = tid + it * 256;      // 0..2047
            int arr  = e >> 10;             // 0 A, 1 W
            int rem  = e & 1023;
            int row  = rem >> 3;
            int c    = rem & 7;
            const __half* g = (arr == 0)
                ? A + (size_t)(m0 + row) * KDIM + k0 + c * 8
                : W + (size_t)(n0 + row) * KDIM + k0 + c * 8;
            cp16(sb + arr * GTILE + row * (LDT * 2) + c * 16, g);
        }
        CP_COMMIT();
    };

    load_stage(0, 0);

    for (int i = 0; i < GNIT; i++) {
        CP_WAIT0();
        __syncthreads();
        // NOTE: 2-stage ping-pong: issue next loads AFTER consuming barrier;
        // loads for i+1 go to the other stage while we compute stage i.
        if (i + 1 < GNIT) load_stage((i + 1) * BKK, (i + 1) & 1);

        const uint32_t sb = smem_base + (i & 1) * GST;
        const uint32_t uA = sb;
        const uint32_t uW = sb + GTILE;

#pragma unroll
        for (int ks = 0; ks < 4; ks++) {
            const int kcol = ks * 16 + kh * 8;

            uint32_t af[4][4];
#pragma unroll
            for (int mt = 0; mt < 4; mt++) {
                int row = mbase + mt * 16 + lr + 8 * half2_;
                ldsm_x4(af[mt][0], af[mt][1], af[mt][2], af[mt][3],
                        uA + (uint32_t)(row * LDT + kcol) * 2);
            }
            uint32_t bf[4][2];
#pragma unroll
            for (int ntp = 0; ntp < 2; ntp++) {
                int row = nbase + ntp * 16 + lr + 8 * half2_;
                uint32_t r0, r1, r2, r3;
                ldsm_x4(r0, r1, r2, r3, uW + (uint32_t)(row * LDT + kcol) * 2);
                bf[ntp * 2 + 0][0] = r0; bf[ntp * 2 + 0][1] = r2;
                bf[ntp * 2 + 1][0] = r1; bf[ntp * 2 + 1][1] = r3;
            }
#pragma unroll
            for (int mt = 0; mt < 4; mt++)
#pragma unroll
                for (int nt = 0; nt < 4; nt++)
                    mma16816(acc[mt][nt], af[mt], bf[nt]);
        }
        __syncthreads();   // stage reuse guard (2-stage)
    }

    const int erow = lid >> 2;
    const int ecol = (lid & 3) * 2;
#pragma unroll
    for (int mt = 0; mt < 4; mt++) {
#pragma unroll
        for (int nt = 0; nt < 4; nt++) {
            int gm = m0 + mbase + mt * 16 + erow;
            int nc = nbase + nt * 8 + ecol;
            int gn = n0 + nc;
            float v0 = (acc[mt][nt][0] + s_bias[nc])     * scale;
            float v1 = (acc[mt][nt][1] + s_bias[nc + 1]) * scale;
            float v2 = (acc[mt][nt][2] + s_bias[nc])     * scale;
            float v3 = (acc[mt][nt][3] + s_bias[nc + 1]) * scale;
            if (Ch) {
                *(uint32_t*)&Ch[(size_t)gm * D_MODEL + gn]       = packh2(v0, v1);
                *(uint32_t*)&Ch[(size_t)(gm + 8) * D_MODEL + gn] = packh2(v2, v3);
            } else {
                *(float2*)&Cf[(size_t)gm * D_MODEL + gn]       = make_float2(v0, v1);
                *(float2*)&Cf[(size_t)(gm + 8) * D_MODEL + gn] = make_float2(v2, v3);
            }
        }
    }
}

__global__ __launch_bounds__(256, 2)
void qk_gemm_kernel(const float* __restrict__ bq, const float* __restrict__ bk)
{
    if (blockIdx.z == 0)
        gemm_core(g_Hh, g_Wqh, bq, QK_SCALE, nullptr, g_Qh);
    else
        gemm_core(g_Hh, g_Wkh, bk, 1.0f, nullptr, g_Kh);
}

__global__ __launch_bounds__(256, 2)
void out_gemm_kernel(const float* __restrict__ bo, float* __restrict__ out)
{
    gemm_core(g_AOh, g_Woh, bo, 1.0f, out, nullptr);
}

// ---------------------------------------------------------------------------
// HMMA flash attention (unchanged r14 config: 3-stage, 128-key stages,
// voted rescale, f16x2 exp, ones-MMA row sums).
// grid (32 = B*NH, 16 = SEQ/128), 256 threads (8 warps), 128 q-rows per CTA.
// ---------------------------------------------------------------------------
#define SLDT 72                        // 144 B row
#define AARR (128 * SLDT * 2)          // 18432 B per array (K or V)
#define AST  (2 * AARR)                // 36864 B per stage
#define NSTG (SEQ / 128)               // 16 stages

__global__ __launch_bounds__(256, 1)
void attn_mma_kernel()
{
    extern __shared__ char dsm[];
    __half* pool = (__half*)dsm;

    const int tid = threadIdx.x;
    const int wid = tid >> 5;
    const int lid = tid & 31;
    const int b   = blockIdx.x >> 4;
    const int h   = blockIdx.x & 15;
    const int q0  = blockIdx.y * 128;

    const int lr     = lid & 7;
    const int half2_ = (lid >> 3) & 1;
    const int kh     = (lid >> 4) & 1;

    const uint32_t smem_base = smem_to_u32(dsm);

    // ---- stage Q tile (128 x 64) through stage-0 area, extract frags ----
#pragma unroll
    for (int i = 0; i < 4; i++) {
        int e   = tid + i * 256;            // 0..1023
        int row = e >> 3;
        int c   = e & 7;
        const __half* src = g_Qh
            + (size_t)(b * SEQ + q0 + row) * D_MODEL + h * HDIM + c * 8;
        *(uint4*)(pool + row * SLDT + c * 8) = *(const uint4*)src;
    }
    __syncthreads();

    uint32_t qh[4][4];
    {
        const int wr = wid * 16;
#pragma unroll
        for (int kc = 0; kc < 4; kc++) {
            int row = wr + lr + 8 * half2_;
            int col = kc * 16 + kh * 8;
            ldsm_x4(qh[kc][0], qh[kc][1], qh[kc][2], qh[kc][3],
                    smem_base + (uint32_t)(row * SLDT + col) * 2);
        }
    }
    __syncthreads();

    float oacc[8][4];
#pragma unroll
    for (int nt = 0; nt < 8; nt++)
#pragma unroll
        for (int c = 0; c < 4; c++) oacc[nt][c] = 0.0f;
    float lacc[4] = {0.0f, 0.0f, 0.0f, 0.0f};
    float mx0 = -1e30f, mx1 = -1e30f;

    const uint32_t ones2[2] = {0x3C003C00u, 0x3C003C00u};

    auto load_stage = [&](int st, int s) {
        const int kb = st * 128;
        uint32_t sb = smem_base + s * AST;
#pragma unroll
        for (int i = 0; i < 8; i++) {
            int arr = i >> 2;                       // 0 K, 1 V
            int rem = ((i & 3) << 8) + tid;         // 0..1023
            int row = rem >> 3;                     // 0..127
            int c   = rem & 7;
            const __half* g = (arr == 0 ? g_Kh : g_Hh)
                + (size_t)(b * SEQ + kb + row) * D_MODEL + h * HDIM + c * 8;
            cp16(sb + arr * AARR + row * (SLDT * 2) + c * 16, g);
        }
        CP_COMMIT();
    };

    load_stage(0, 0);
    load_stage(1, 1);

    for (int st = 0; st < NSTG; st++) {
        if (st + 1 < NSTG) { CP_WAIT1(); } else { CP_WAIT0(); }
        __syncthreads();
        if (st + 2 < NSTG) load_stage(st + 2, (st + 2) % 3);

        const uint32_t sbs = smem_base + (st % 3) * AST;

#pragma unroll
        for (int sub = 0; sub < 2; sub++) {
            const uint32_t uK = sbs + (uint32_t)(sub * 64 * SLDT) * 2;
            const uint32_t uV = sbs + AARR + (uint32_t)(sub * 64 * SLDT) * 2;

            // ---- S = Q K^T ----
            float S[8][4];
#pragma unroll
            for (int nt = 0; nt < 8; nt++)
#pragma unroll
                for (int c = 0; c < 4; c++) S[nt][c] = 0.0f;

#pragma unroll
            for (int kc = 0; kc < 4; kc++) {
                uint32_t kb_[8][2];
#pragma unroll
                for (int ng = 0; ng < 4; ng++) {
                    int row = ng * 16 + lr + 8 * half2_;
                    int col = kc * 16 + kh * 8;
                    uint32_t r0, r1, r2, r3;
                    ldsm_x4(r0, r1, r2, r3, uK + (uint32_t)(row * SLDT + col) * 2);
                    kb_[ng * 2 + 0][0] = r0; kb_[ng * 2 + 0][1] = r2;
                    kb_[ng * 2 + 1][0] = r1; kb_[ng * 2 + 1][1] = r3;
                }
#pragma unroll
                for (int nt = 0; nt < 8; nt++)
                    mma16816(S[nt], qh[kc], kb_[nt]);
            }

            // ---- online softmax (voted conditional rescale) ----
            float tm0 = -1e30f, tm1 = -1e30f;
#pragma unroll
            for (int nt = 0; nt < 8; nt++) {
                tm0 = fmaxf(tm0, fmaxf(S[nt][0], S[nt][1]));
                tm1 = fmaxf(tm1, fmaxf(S[nt][2], S[nt][3]));
            }
            tm0 = fmaxf(tm0, __shfl_xor_sync(0xffffffffu, tm0, 1));
            tm0 = fmaxf(tm0, __shfl_xor_sync(0xffffffffu, tm0, 2));
            tm1 = fmaxf(tm1, __shfl_xor_sync(0xffffffffu, tm1, 1));
            tm1 = fmaxf(tm1, __shfl_xor_sync(0xffffffffu, tm1, 2));

            bool grew = (tm0 > mx0) || (tm1 > mx1);
            if (__any_sync(0xffffffffu, grew)) {
                float mn0 = fmaxf(mx0, tm0), mn1 = fmaxf(mx1, tm1);
                float a0 = ex2f(mx0 - mn0), a1 = ex2f(mx1 - mn1);
                lacc[0] *= a0; lacc[1] *= a0;
                lacc[2] *= a1; lacc[3] *= a1;
#pragma unroll
                for (int nt = 0; nt < 8; nt++) {
                    oacc[nt][0] *= a0; oacc[nt][1] *= a0;
                    oacc[nt][2] *= a1; oacc[nt][3] *= a1;
                }
                mx0 = mn0; mx1 = mn1;
            }

            // ---- P = exp2(S - mx) via f16x2 MUFU ----
            uint32_t pa[4][4];
#pragma unroll
            for (int j = 0; j < 4; j++) {
#pragma unroll
                for (int sg = 0; sg < 2; sg++) {
                    int t2 = j * 2 + sg;
                    pa[j][sg * 2 + 0] = h2exp2u(packh2(S[t2][0] - mx0, S[t2][1] - mx0));
                    pa[j][sg * 2 + 1] = h2exp2u(packh2(S[t2][2] - mx1, S[t2][3] - mx1));
                }
            }

            // ---- O += P V ; l += P 1 ----
#pragma unroll
            for (int kc = 0; kc < 4; kc++) {
                uint32_t vb[8][2];
#pragma unroll
                for (int dg = 0; dg < 4; dg++) {
                    int rowk = kc * 16 + lr + 8 * half2_;
                    int dimc = dg * 16 + kh * 8;
                    uint32_t r0, r1, r2, r3;
                    ldsm_x4_t(r0, r1, r2, r3, uV + (uint32_t)(rowk * SLDT + dimc) * 2);
                    vb[dg * 2 + 0][0] = r0; vb[dg * 2 + 0][1] = r1;
                    vb[dg * 2 + 1][0] = r2; vb[dg * 2 + 1][1] = r3;
                }
                mma16816(lacc, pa[kc], ones2);
#pragma unroll
                for (int nt = 0; nt < 8; nt++)
                    mma16816(oacc[nt], pa[kc], vb[nt]);
            }
        }
    }

    // ---- epilogue ----
    const float inv0 = 1.0f / lacc[0];
    const float inv1 = 1.0f / lacc[2];
    const int gr  = b * SEQ + q0 + wid * 16 + (lid >> 2);
    const int col = h * HDIM + (lid & 3) * 2;
#pragma unroll
    for (int nt = 0; nt < 8; nt++) {
        int gc = col + nt * 8;
        float v0 = oacc[nt][0] * inv0, v1 = oacc[nt][1] * inv0;
        float v2 = oacc[nt][2] * inv1, v3 = oacc[nt][3] * inv1;
        *(uint32_t*)&g_AOh[(size_t)gr * D_MODEL + gc]       = packh2(v0, v1);
        *(uint32_t*)&g_AOh[(size_t)(gr + 8) * D_MODEL + gc] = packh2(v2, v3);
    }
}

// ---------------------------------------------------------------------------
extern "C" void kernel_launch(void* const* d_in, const int* in_sizes, int n_in,
                              void* d_out, int out_size)
{
    (void)in_sizes; (void)n_in; (void)out_size;
    const float* H  = (const float*)d_in[0];
    const float* Wq = (const float*)d_in[1];
    const float* bq = (const float*)d_in[2];
    const float* Wk = (const float*)d_in[3];
    const float* bk = (const float*)d_in[4];
    const float* Wo = (const float*)d_in[5];
    const float* bo = (const float*)d_in[6];
    float* out = (float*)d_out;

    void *p_Hh, *p_Wqh, *p_Wkh, *p_Woh;
    cudaGetSymbolAddress(&p_Hh,  g_Hh);
    cudaGetSymbolAddress(&p_Wqh, g_Wqh);
    cudaGetSymbolAddress(&p_Wkh, g_Wkh);
    cudaGetSymbolAddress(&p_Woh, g_Woh);

    const int GSMEM = 2 * GST;    // 73,728 B  (2-stage -> 2 CTAs/SM)
    const int ASMEM = 3 * AST;    // 110,592 B (attention unchanged)

    cudaFuncSetAttribute(qk_gemm_kernel,
                         cudaFuncAttributeMaxDynamicSharedMemorySize, GSMEM);
    cudaFuncSetAttribute(out_gemm_kernel,
                         cudaFuncAttributeMaxDynamicSharedMemorySize, GSMEM);
    cudaFuncSetAttribute(attn_mma_kernel,
                         cudaFuncAttributeMaxDynamicSharedMemorySize, ASMEM);

    const int nH4 = NROWS * D_MODEL / 4;      // 1,048,576
    const int nW4 = D_MODEL * D_MODEL / 4;    // 262,144
    const int nTot = nH4 + 3 * nW4;           // 1,835,008

    cast4_kernel<<<(nTot + 255) / 256, 256>>>(
        (const float4*)H,  (uint2*)p_Hh,  nH4,
        (const float4*)Wq, (uint2*)p_Wqh, nW4,
        (const float4*)Wk, (uint2*)p_Wkh, nW4,
        (const float4*)Wo, (uint2*)p_Woh, nW4);

    dim3 ggrid(D_MODEL / BN, NROWS / BM, 2);   // (8, 32, 2)
    qk_gemm_kernel<<<ggrid, 256, GSMEM>>>(bq, bk);

    dim3 agrid(BATCH * NHEADS, SEQ / 128);     // (32, 16)
    attn_mma_kernel<<<agrid, 256, ASMEM>>>();

    dim3 ogrid(D_MODEL / BN, NROWS / BM, 1);   // (8, 32)
    out_gemm_kernel<<<ogrid, 256, GSMEM>>>(bo, out);
}

// round 16
// speedup vs baseline: 1.1148x; 1.0454x over previous
#include <cuda_runtime.h>
#include <cuda_fp16.h>
#include <cstdint>

#define D_MODEL 1024
#define NHEADS  16
#define HDIM    64
#define BATCH   2
#define SEQ     2048
#define NROWS   (BATCH * SEQ)     // 4096
#define KDIM    D_MODEL

// softmax scale folded into Q projection: 1/sqrt(64) * log2(e)
#define QK_SCALE 0.1803368801111244f

// ---------------------------------------------------------------------------
// Scratch (device globals)
// ---------------------------------------------------------------------------
__device__ __half g_Hh [NROWS * D_MODEL];   // H, also V in attention
__device__ __half g_Qh [NROWS * D_MODEL];
__device__ __half g_Kh [NROWS * D_MODEL];
__device__ __half g_AOh[NROWS * D_MODEL];
__device__ __half g_Wqh[D_MODEL * D_MODEL];
__device__ __half g_Wkh[D_MODEL * D_MODEL];
__device__ __half g_Woh[D_MODEL * D_MODEL];

// ---------------------------------------------------------------------------
// helpers
// ---------------------------------------------------------------------------
__device__ __forceinline__ uint32_t smem_to_u32(const void* p) {
    uint32_t a;
    asm("{ .reg .u64 t; cvta.to.shared.u64 t, %1; cvt.u32.u64 %0, t; }"
        : "=r"(a) : "l"(p));
    return a;
}
__device__ __forceinline__ void ldsm_x4(uint32_t& r0, uint32_t& r1,
                                        uint32_t& r2, uint32_t& r3, uint32_t addr) {
    asm volatile("ldmatrix.sync.aligned.m8n8.x4.shared.b16 {%0,%1,%2,%3}, [%4];"
                 : "=r"(r0), "=r"(r1), "=r"(r2), "=r"(r3) : "r"(addr));
}
__device__ __forceinline__ void ldsm_x4_t(uint32_t& r0, uint32_t& r1,
                                          uint32_t& r2, uint32_t& r3, uint32_t addr) {
    asm volatile("ldmatrix.sync.aligned.m8n8.x4.trans.shared.b16 {%0,%1,%2,%3}, [%4];"
                 : "=r"(r0), "=r"(r1), "=r"(r2), "=r"(r3) : "r"(addr));
}
__device__ __forceinline__ void mma16816(float* c, const uint32_t* a,
                                         const uint32_t* b) {
    asm volatile(
        "mma.sync.aligned.m16n8k16.row.col.f32.f16.f16.f32 "
        "{%0,%1,%2,%3}, {%4,%5,%6,%7}, {%8,%9}, {%0,%1,%2,%3};"
        : "+f"(c[0]), "+f"(c[1]), "+f"(c[2]), "+f"(c[3])
        : "r"(a[0]), "r"(a[1]), "r"(a[2]), "r"(a[3]), "r"(b[0]), "r"(b[1]));
}
__device__ __forceinline__ float ex2f(float x) {
    float r;
    asm("ex2.approx.ftz.f32 %0, %1;" : "=f"(r) : "f"(x));
    return r;
}
__device__ __forceinline__ uint32_t h2exp2u(uint32_t x) {
    uint32_t r;
    asm("ex2.approx.f16x2 %0, %1;" : "=r"(r) : "r"(x));
    return r;
}
__device__ __forceinline__ uint32_t packh2(float a, float b) {
    __half2 t = __floats2half2_rn(a, b);
    return *(uint32_t*)&t;
}
__device__ __forceinline__ void cp16(uint32_t smem, const void* g) {
    asm volatile("cp.async.cg.shared.global [%0], [%1], 16;"
                 :: "r"(smem), "l"(g) : "memory");
}
#define CP_COMMIT() asm volatile("cp.async.commit_group;" ::: "memory")
#define CP_WAIT0()  asm volatile("cp.async.wait_group 0;" ::: "memory")

// ---------------------------------------------------------------------------
// fp32 -> fp16 cast, 4 tensors in one launch
// ---------------------------------------------------------------------------
__device__ __forceinline__ void cast4_do(const float4* src, uint2* hi, int i)
{
    float4 v = src[i];
    hi[i] = make_uint2(packh2(v.x, v.y), packh2(v.z, v.w));
}

__global__ __launch_bounds__(256)
void cast4_kernel(const float4* s0, uint2* h0, int n0,
                  const float4* s1, uint2* h1, int n1,
                  const float4* s2, uint2* h2, int n2,
                  const float4* s3, uint2* h3, int n3)
{
    int i = blockIdx.x * blockDim.x + threadIdx.x;
    if (i < n0) { cast4_do(s0, h0, i); return; }
    i -= n0;
    if (i < n1) { cast4_do(s1, h1, i); return; }
    i -= n1;
    if (i < n2) { cast4_do(s2, h2, i); return; }
    i -= n2;
    if (i < n3) { cast4_do(s3, h3, i); }
}

// ---------------------------------------------------------------------------
// HMMA GEMM (1-pass fp16): C = A*W^T + bias.
// CTA 128x128, BK=64, 256 threads (8 warps), 2-stage cp.async pipeline.
// ---------------------------------------------------------------------------
#define BM 128
#define BN 128
#define BKK 64
#define LDT 72                     // 144 B row (9 x 16B) -> LDSM conflict-free
#define GTILE (BM * LDT * 2)       // 18432 B per array
#define GST   (2 * GTILE)          // A + W per stage
#define GNIT  (KDIM / BKK)         // 16

__device__ __forceinline__ void gemm_core(
    const __half* __restrict__ A, const __half* __restrict__ W,
    const float* __restrict__ bias, float scale,
    float* __restrict__ Cf, __half* __restrict__ Ch)
{
    extern __shared__ char dsm[];
    __shared__ float s_bias[BN];

    const int tid = threadIdx.x;
    const int wid = tid >> 5;
    const int lid = tid & 31;
    const int wm  = wid & 1;
    const int wn  = wid >> 1;
    const int m0  = blockIdx.y * BM;
    const int n0  = blockIdx.x * BN;

    if (tid < BN) s_bias[tid] = bias[n0 + tid];

    const int lr     = lid & 7;
    const int half2_ = (lid >> 3) & 1;
    const int kh     = (lid >> 4) & 1;
    const int mbase  = wm * 64;
    const int nbase  = wn * 32;

    const uint32_t smem_base = smem_to_u32(dsm);

    float acc[4][4][4];
#pragma unroll
    for (int i = 0; i < 4; i++)
#pragma unroll
        for (int j = 0; j < 4; j++)
#pragma unroll
            for (int c = 0; c < 4; c++) acc[i][j][c] = 0.0f;

    auto load_stage = [&](int k0, int s) {
        uint32_t sb = smem_base + s * GST;
#pragma unroll
        for (int it = 0; it < 8; it++) {
            int e    = tid + it * 256;      // 0..2047
            int arr  = e >> 10;             // 0 A, 1 W
            int rem  = e & 1023;
            int row  = rem >> 3;
            int c    = rem & 7;
            const __half* g = (arr == 0)
                ? A + (size_t)(m0 + row) * KDIM + k0 + c * 8
                : W + (size_t)(n0 + row) * KDIM + k0 + c * 8;
            cp16(sb + arr * GTILE + row * (LDT * 2) + c * 16, g);
        }
        CP_COMMIT();
    };

    load_stage(0, 0);

    for (int i = 0; i < GNIT; i++) {
        CP_WAIT0();
        __syncthreads();
        if (i + 1 < GNIT) load_stage((i + 1) * BKK, (i + 1) & 1);

        const uint32_t sb = smem_base + (i & 1) * GST;
        const uint32_t uA = sb;
        const uint32_t uW = sb + GTILE;

#pragma unroll
        for (int ks = 0; ks < 4; ks++) {
            const int kcol = ks * 16 + kh * 8;

            uint32_t af[4][4];
#pragma unroll
            for (int mt = 0; mt < 4; mt++) {
                int row = mbase + mt * 16 + lr + 8 * half2_;
                ldsm_x4(af[mt][0], af[mt][1], af[mt][2], af[mt][3],
                        uA + (uint32_t)(row * LDT + kcol) * 2);
            }
            uint32_t bf[4][2];
#pragma unroll
            for (int ntp = 0; ntp < 2; ntp++) {
                int row = nbase + ntp * 16 + lr + 8 * half2_;
                uint32_t r0, r1, r2, r3;
                ldsm_x4(r0, r1, r2, r3, uW + (uint32_t)(row * LDT + kcol) * 2);
                bf[ntp * 2 + 0][0] = r0; bf[ntp * 2 + 0][1] = r2;
                bf[ntp * 2 + 1][0] = r1; bf[ntp * 2 + 1][1] = r3;
            }
#pragma unroll
            for (int mt = 0; mt < 4; mt++)
#pragma unroll
                for (int nt = 0; nt < 4; nt++)
                    mma16816(acc[mt][nt], af[mt], bf[nt]);
        }
        __syncthreads();
    }

    const int erow = lid >> 2;
    const int ecol = (lid & 3) * 2;
#pragma unroll
    for (int mt = 0; mt < 4; mt++) {
#pragma unroll
        for (int nt = 0; nt < 4; nt++) {
            int gm = m0 + mbase + mt * 16 + erow;
            int nc = nbase + nt * 8 + ecol;
            int gn = n0 + nc;
            float v0 = (acc[mt][nt][0] + s_bias[nc])     * scale;
            float v1 = (acc[mt][nt][1] + s_bias[nc + 1]) * scale;
            float v2 = (acc[mt][nt][2] + s_bias[nc])     * scale;
            float v3 = (acc[mt][nt][3] + s_bias[nc + 1]) * scale;
            if (Ch) {
                *(uint32_t*)&Ch[(size_t)gm * D_MODEL + gn]       = packh2(v0, v1);
                *(uint32_t*)&Ch[(size_t)(gm + 8) * D_MODEL + gn] = packh2(v2, v3);
            } else {
                *(float2*)&Cf[(size_t)gm * D_MODEL + gn]       = make_float2(v0, v1);
                *(float2*)&Cf[(size_t)(gm + 8) * D_MODEL + gn] = make_float2(v2, v3);
            }
        }
    }
}

__global__ __launch_bounds__(256, 2)
void qk_gemm_kernel(const float* __restrict__ bq, const float* __restrict__ bk)
{
    if (blockIdx.z == 0)
        gemm_core(g_Hh, g_Wqh, bq, QK_SCALE, nullptr, g_Qh);
    else
        gemm_core(g_Hh, g_Wkh, bk, 1.0f, nullptr, g_Kh);
}

__global__ __launch_bounds__(256, 2)
void out_gemm_kernel(const float* __restrict__ bo, float* __restrict__ out)
{
    gemm_core(g_AOh, g_Woh, bo, 1.0f, out, nullptr);
}

// ---------------------------------------------------------------------------
// HMMA flash attention, fine-grained: CTA = 64 q-rows, 256 threads.
// Warps 0-3 process keys [0,64) of each 128-key stage; warps 4-7 keys [64,128).
// Independent (m,l,O) per warp-group; exact two-way merge at the end.
// grid (32 = B*NH, 32 = SEQ/64) = 1024 CTAs. 2-stage cp.async pipeline.
// ---------------------------------------------------------------------------
#define SLDT 72                        // 144 B row
#define AARR (128 * SLDT * 2)          // 18432 B per array (K or V)
#define AST  (2 * AARR)                // 36864 B per stage
#define NSTG (SEQ / 128)               // 16 stages

__global__ __launch_bounds__(256, 1)
void attn_mma_kernel()
{
    extern __shared__ char dsm[];
    __half* pool = (__half*)dsm;

    const int tid = threadIdx.x;
    const int wid = tid >> 5;
    const int lid = tid & 31;
    const int b   = blockIdx.x >> 4;
    const int h   = blockIdx.x & 15;
    const int q0  = blockIdx.y * 64;

    const int lr     = lid & 7;
    const int half2_ = (lid >> 3) & 1;
    const int kh     = (lid >> 4) & 1;
    const int wq     = wid & 3;        // q-row group within 64
    const int sub    = wid >> 2;       // key sub-tile of each stage

    const uint32_t smem_base = smem_to_u32(dsm);

    // ---- stage Q tile (64 x 64) through stage-0 area, extract frags ----
#pragma unroll
    for (int i = 0; i < 2; i++) {
        int e   = tid + i * 256;            // 0..511
        int row = e >> 3;                   // 0..63
        int c   = e & 7;
        const __half* src = g_Qh
            + (size_t)(b * SEQ + q0 + row) * D_MODEL + h * HDIM + c * 8;
        *(uint4*)(pool + row * SLDT + c * 8) = *(const uint4*)src;
    }
    __syncthreads();

    uint32_t qh[4][4];
    {
        const int wr = wq * 16;
#pragma unroll
        for (int kc = 0; kc < 4; kc++) {
            int row = wr + lr + 8 * half2_;
            int col = kc * 16 + kh * 8;
            ldsm_x4(qh[kc][0], qh[kc][1], qh[kc][2], qh[kc][3],
                    smem_base + (uint32_t)(row * SLDT + col) * 2);
        }
    }
    __syncthreads();

    float oacc[8][4];
#pragma unroll
    for (int nt = 0; nt < 8; nt++)
#pragma unroll
        for (int c = 0; c < 4; c++) oacc[nt][c] = 0.0f;
    float lacc[4] = {0.0f, 0.0f, 0.0f, 0.0f};
    float mx0 = -1e30f, mx1 = -1e30f;

    const uint32_t ones2[2] = {0x3C003C00u, 0x3C003C00u};

    auto load_stage = [&](int st, int s) {
        const int kb = st * 128;
        uint32_t sb = smem_base + s * AST;
#pragma unroll
        for (int i = 0; i < 8; i++) {
            int arr = i >> 2;                       // 0 K, 1 V
            int rem = ((i & 3) << 8) + tid;         // 0..1023
            int row = rem >> 3;                     // 0..127
            int c   = rem & 7;
            const __half* g = (arr == 0 ? g_Kh : g_Hh)
                + (size_t)(b * SEQ + kb + row) * D_MODEL + h * HDIM + c * 8;
            cp16(sb + arr * AARR + row * (SLDT * 2) + c * 16, g);
        }
        CP_COMMIT();
    };

    load_stage(0, 0);

    for (int st = 0; st < NSTG; st++) {
        CP_WAIT0();
        __syncthreads();
        if (st + 1 < NSTG) load_stage(st + 1, (st + 1) & 1);

        const uint32_t sbs = smem_base + (st & 1) * AST;
        const uint32_t uK = sbs + (uint32_t)(sub * 64 * SLDT) * 2;
        const uint32_t uV = sbs + AARR + (uint32_t)(sub * 64 * SLDT) * 2;

        // ---- S = Q K^T ----
        float S[8][4];
#pragma unroll
        for (int nt = 0; nt < 8; nt++)
#pragma unroll
            for (int c = 0; c < 4; c++) S[nt][c] = 0.0f;

#pragma unroll
        for (int kc = 0; kc < 4; kc++) {
            uint32_t kb_[8][2];
#pragma unroll
            for (int ng = 0; ng < 4; ng++) {
                int row = ng * 16 + lr + 8 * half2_;
                int col = kc * 16 + kh * 8;
                uint32_t r0, r1, r2, r3;
                ldsm_x4(r0, r1, r2, r3, uK + (uint32_t)(row * SLDT + col) * 2);
                kb_[ng * 2 + 0][0] = r0; kb_[ng * 2 + 0][1] = r2;
                kb_[ng * 2 + 1][0] = r1; kb_[ng * 2 + 1][1] = r3;
            }
#pragma unroll
            for (int nt = 0; nt < 8; nt++)
                mma16816(S[nt], qh[kc], kb_[nt]);
        }

        // ---- online softmax (voted conditional rescale) ----
        float tm0 = -1e30f, tm1 = -1e30f;
#pragma unroll
        for (int nt = 0; nt < 8; nt++) {
            tm0 = fmaxf(tm0, fmaxf(S[nt][0], S[nt][1]));
            tm1 = fmaxf(tm1, fmaxf(S[nt][2], S[nt][3]));
        }
        tm0 = fmaxf(tm0, __shfl_xor_sync(0xffffffffu, tm0, 1));
        tm0 = fmaxf(tm0, __shfl_xor_sync(0xffffffffu, tm0, 2));
        tm1 = fmaxf(tm1, __shfl_xor_sync(0xffffffffu, tm1, 1));
        tm1 = fmaxf(tm1, __shfl_xor_sync(0xffffffffu, tm1, 2));

        bool grew = (tm0 > mx0) || (tm1 > mx1);
        if (__any_sync(0xffffffffu, grew)) {
            float mn0 = fmaxf(mx0, tm0), mn1 = fmaxf(mx1, tm1);
            float a0 = ex2f(mx0 - mn0), a1 = ex2f(mx1 - mn1);
            lacc[0] *= a0; lacc[1] *= a0;
            lacc[2] *= a1; lacc[3] *= a1;
#pragma unroll
            for (int nt = 0; nt < 8; nt++) {
                oacc[nt][0] *= a0; oacc[nt][1] *= a0;
                oacc[nt][2] *= a1; oacc[nt][3] *= a1;
            }
            mx0 = mn0; mx1 = mn1;
        }

        // ---- P = exp2(S - mx) via f16x2 MUFU ----
        uint32_t pa[4][4];
#pragma unroll
        for (int j = 0; j < 4; j++) {
#pragma unroll
            for (int sg = 0; sg < 2; sg++) {
                int t2 = j * 2 + sg;
                pa[j][sg * 2 + 0] = h2exp2u(packh2(S[t2][0] - mx0, S[t2][1] - mx0));
                pa[j][sg * 2 + 1] = h2exp2u(packh2(S[t2][2] - mx1, S[t2][3] - mx1));
            }
        }

        // ---- O += P V ; l += P 1 ----
#pragma unroll
        for (int kc = 0; kc < 4; kc++) {
            uint32_t vb[8][2];
#pragma unroll
            for (int dg = 0; dg < 4; dg++) {
                int rowk = kc * 16 + lr + 8 * half2_;
                int dimc = dg * 16 + kh * 8;
                uint32_t r0, r1, r2, r3;
                ldsm_x4_t(r0, r1, r2, r3, uV + (uint32_t)(rowk * SLDT + dimc) * 2);
                vb[dg * 2 + 0][0] = r0; vb[dg * 2 + 0][1] = r1;
                vb[dg * 2 + 1][0] = r2; vb[dg * 2 + 1][1] = r3;
            }
            mma16816(lacc, pa[kc], ones2);
#pragma unroll
            for (int nt = 0; nt < 8; nt++)
                mma16816(oacc[nt], pa[kc], vb[nt]);
        }
    }

    // ---- merge warp-group halves (exact two-way softmax combine) ----
    __syncthreads();
    float* buf = (float*)dsm;           // 128 threads x 36 floats = 18,432 B
    if (wid >= 4) {
        int base = (tid - 128) * 36;
        buf[base + 0] = mx0; buf[base + 1] = mx1;
        buf[base + 2] = lacc[0]; buf[base + 3] = lacc[2];
#pragma unroll
        for (int nt = 0; nt < 8; nt++)
#pragma unroll
            for (int c = 0; c < 4; c++)
                buf[base + 4 + nt * 4 + c] = oacc[nt][c];
    }
    __syncthreads();

    if (wid < 4) {
        int base = tid * 36;
        float mB0 = buf[base + 0], mB1 = buf[base + 1];
        float lB0 = buf[base + 2], lB1 = buf[base + 3];
        float m0 = fmaxf(mx0, mB0), m1 = fmaxf(mx1, mB1);
        float wA0 = ex2f(mx0 - m0), wB0 = ex2f(mB0 - m0);
        float wA1 = ex2f(mx1 - m1), wB1 = ex2f(mB1 - m1);
        float inv0 = 1.0f / (lacc[0] * wA0 + lB0 * wB0);
        float inv1 = 1.0f / (lacc[2] * wA1 + lB1 * wB1);

        const int gr  = b * SEQ + q0 + wq * 16 + (lid >> 2);
        const int col = h * HDIM + (lid & 3) * 2;
#pragma unroll
        for (int nt = 0; nt < 8; nt++) {
            int gc = col + nt * 8;
            float v0 = (oacc[nt][0] * wA0 + buf[base + 4 + nt * 4 + 0] * wB0) * inv0;
            float v1 = (oacc[nt][1] * wA0 + buf[base + 4 + nt * 4 + 1] * wB0) * inv0;
            float v2 = (oacc[nt][2] * wA1 + buf[base + 4 + nt * 4 + 2] * wB1) * inv1;
            float v3 = (oacc[nt][3] * wA1 + buf[base + 4 + nt * 4 + 3] * wB1) * inv1;
            *(uint32_t*)&g_AOh[(size_t)gr * D_MODEL + gc]       = packh2(v0, v1);
            *(uint32_t*)&g_AOh[(size_t)(gr + 8) * D_MODEL + gc] = packh2(v2, v3);
        }
    }
}

// ---------------------------------------------------------------------------
extern "C" void kernel_launch(void* const* d_in, const int* in_sizes, int n_in,
                              void* d_out, int out_size)
{
    (void)in_sizes; (void)n_in; (void)out_size;
    const float* H  = (const float*)d_in[0];
    const float* Wq = (const float*)d_in[1];
    const float* bq = (const float*)d_in[2];
    const float* Wk = (const float*)d_in[3];
    const float* bk = (const float*)d_in[4];
    const float* Wo = (const float*)d_in[5];
    const float* bo = (const float*)d_in[6];
    float* out = (float*)d_out;

    void *p_Hh, *p_Wqh, *p_Wkh, *p_Woh;
    cudaGetSymbolAddress(&p_Hh,  g_Hh);
    cudaGetSymbolAddress(&p_Wqh, g_Wqh);
    cudaGetSymbolAddress(&p_Wkh, g_Wkh);
    cudaGetSymbolAddress(&p_Woh, g_Woh);

    const int GSMEM = 2 * GST;    // 73,728 B
    const int ASMEM = 2 * AST;    // 73,728 B

    cudaFuncSetAttribute(qk_gemm_kernel,
                         cudaFuncAttributeMaxDynamicSharedMemorySize, GSMEM);
    cudaFuncSetAttribute(out_gemm_kernel,
                         cudaFuncAttributeMaxDynamicSharedMemorySize, GSMEM);
    cudaFuncSetAttribute(attn_mma_kernel,
                         cudaFuncAttributeMaxDynamicSharedMemorySize, ASMEM);

    const int nH4 = NROWS * D_MODEL / 4;      // 1,048,576
    const int nW4 = D_MODEL * D_MODEL / 4;    // 262,144
    const int nTot = nH4 + 3 * nW4;           // 1,835,008

    cast4_kernel<<<(nTot + 255) / 256, 256>>>(
        (const float4*)H,  (uint2*)p_Hh,  nH4,
        (const float4*)Wq, (uint2*)p_Wqh, nW4,
        (const float4*)Wk, (uint2*)p_Wkh, nW4,
        (const float4*)Wo, (uint2*)p_Woh, nW4);

    dim3 ggrid(D_MODEL / BN, NROWS / BM, 2);   // (8, 32, 2)
    qk_gemm_kernel<<<ggrid, 256, GSMEM>>>(bq, bk);

    dim3 agrid(BATCH * NHEADS, SEQ / 64);      // (32, 32) = 1024 CTAs
    attn_mma_kernel<<<agrid, 256, ASMEM>>>();

    dim3 ogrid(D_MODEL / BN, NROWS / BM, 1);   // (8, 32)
    out_gemm_kernel<<<ogrid, 256, GSMEM>>>(bo, out);
}

// round 17
// speedup vs baseline: 1.1246x; 1.0088x over previous
#include <cuda_runtime.h>
#include <cuda_fp16.h>
#include <cstdint>

#define D_MODEL 1024
#define NHEADS  16
#define HDIM    64
#define BATCH   2
#define SEQ     2048
#define NROWS   (BATCH * SEQ)     // 4096
#define KDIM    D_MODEL

// softmax scale folded into Q projection: 1/sqrt(64) * log2(e)
#define QK_SCALE 0.1803368801111244f

// ---------------------------------------------------------------------------
// Scratch (device globals)
// ---------------------------------------------------------------------------
__device__ __half g_Hh [NROWS * D_MODEL];   // H, also V in attention
__device__ __half g_Qh [NROWS * D_MODEL];
__device__ __half g_Kh [NROWS * D_MODEL];
__device__ __half g_AOh[NROWS * D_MODEL];
__device__ __half g_Wqh[D_MODEL * D_MODEL];
__device__ __half g_Wkh[D_MODEL * D_MODEL];
__device__ __half g_Woh[D_MODEL * D_MODEL];

// ---------------------------------------------------------------------------
// helpers
// ---------------------------------------------------------------------------
__device__ __forceinline__ uint32_t smem_to_u32(const void* p) {
    uint32_t a;
    asm("{ .reg .u64 t; cvta.to.shared.u64 t, %1; cvt.u32.u64 %0, t; }"
        : "=r"(a) : "l"(p));
    return a;
}
__device__ __forceinline__ void ldsm_x4(uint32_t& r0, uint32_t& r1,
                                        uint32_t& r2, uint32_t& r3, uint32_t addr) {
    asm volatile("ldmatrix.sync.aligned.m8n8.x4.shared.b16 {%0,%1,%2,%3}, [%4];"
                 : "=r"(r0), "=r"(r1), "=r"(r2), "=r"(r3) : "r"(addr));
}
__device__ __forceinline__ void ldsm_x4_t(uint32_t& r0, uint32_t& r1,
                                          uint32_t& r2, uint32_t& r3, uint32_t addr) {
    asm volatile("ldmatrix.sync.aligned.m8n8.x4.trans.shared.b16 {%0,%1,%2,%3}, [%4];"
                 : "=r"(r0), "=r"(r1), "=r"(r2), "=r"(r3) : "r"(addr));
}
__device__ __forceinline__ void mma16816(float* c, const uint32_t* a,
                                         const uint32_t* b) {
    asm volatile(
        "mma.sync.aligned.m16n8k16.row.col.f32.f16.f16.f32 "
        "{%0,%1,%2,%3}, {%4,%5,%6,%7}, {%8,%9}, {%0,%1,%2,%3};"
        : "+f"(c[0]), "+f"(c[1]), "+f"(c[2]), "+f"(c[3])
        : "r"(a[0]), "r"(a[1]), "r"(a[2]), "r"(a[3]), "r"(b[0]), "r"(b[1]));
}
__device__ __forceinline__ float ex2f(float x) {
    float r;
    asm("ex2.approx.ftz.f32 %0, %1;" : "=f"(r) : "f"(x));
    return r;
}
__device__ __forceinline__ uint32_t h2exp2u(uint32_t x) {
    uint32_t r;
    asm("ex2.approx.f16x2 %0, %1;" : "=r"(r) : "r"(x));
    return r;
}
__device__ __forceinline__ uint32_t packh2(float a, float b) {
    __half2 t = __floats2half2_rn(a, b);
    return *(uint32_t*)&t;
}
__device__ __forceinline__ void cp16(uint32_t smem, const void* g) {
    asm volatile("cp.async.cg.shared.global [%0], [%1], 16;"
                 :: "r"(smem), "l"(g) : "memory");
}
#define CP_COMMIT() asm volatile("cp.async.commit_group;" ::: "memory")
#define CP_WAIT0()  asm volatile("cp.async.wait_group 0;" ::: "memory")

// ---------------------------------------------------------------------------
// fp32 -> fp16 cast, 4 tensors in one launch
// ---------------------------------------------------------------------------
__device__ __forceinline__ void cast4_do(const float4* src, uint2* hi, int i)
{
    float4 v = src[i];
    hi[i] = make_uint2(packh2(v.x, v.y), packh2(v.z, v.w));
}

__global__ __launch_bounds__(256)
void cast4_kernel(const float4* s0, uint2* h0, int n0,
                  const float4* s1, uint2* h1, int n1,
                  const float4* s2, uint2* h2, int n2,
                  const float4* s3, uint2* h3, int n3)
{
    int i = blockIdx.x * blockDim.x + threadIdx.x;
    if (i < n0) { cast4_do(s0, h0, i); return; }
    i -= n0;
    if (i < n1) { cast4_do(s1, h1, i); return; }
    i -= n1;
    if (i < n2) { cast4_do(s2, h2, i); return; }
    i -= n2;
    if (i < n3) { cast4_do(s3, h3, i); }
}

// ---------------------------------------------------------------------------
// HMMA GEMM (1-pass fp16): C = A*W^T + bias.
// Templated N tile: BNv=64 (qk: 1024 CTAs, 4m x 2n warps, 32x32 warp tile)
//                   BNv=128 (out: unchanged 2m x 4n, 64x32 warp tile)
// BM=128, BK=64, 256 threads, 2-stage cp.async pipeline.
// ---------------------------------------------------------------------------
#define BM 128
#define BKK 64
#define LDT 72                     // 144 B row (9 x 16B) -> LDSM conflict-free
#define GTILE_A (BM * LDT * 2)     // 18432 B
#define GNIT  (KDIM / BKK)         // 16

template <int BNv>
__device__ __forceinline__ void gemm_core(
    const __half* __restrict__ A, const __half* __restrict__ W,
    const float* __restrict__ bias, float scale,
    float* __restrict__ Cf, __half* __restrict__ Ch)
{
    constexpr int GTILE_W = BNv * LDT * 2;        // 9216 or 18432
    constexpr int GST     = GTILE_A + GTILE_W;
    constexpr int WMv     = (BNv == 128) ? 2 : 4; // warps along m
    constexpr int MT      = (BM / WMv) / 16;      // m-frags: 4 or 2
    constexpr int NCHUNK  = (1024 + BNv * 8) / 256; // load iters per stage

    extern __shared__ char dsm[];
    __shared__ float s_bias[BNv];

    const int tid = threadIdx.x;
    const int wid = tid >> 5;
    const int lid = tid & 31;
    const int wm  = wid % WMv;
    const int wn  = wid / WMv;
    const int m0  = blockIdx.y * BM;
    const int n0  = blockIdx.x * BNv;

    if (tid < BNv) s_bias[tid] = bias[n0 + tid];

    const int lr     = lid & 7;
    const int half2_ = (lid >> 3) & 1;
    const int kh     = (lid >> 4) & 1;
    const int mbase  = wm * (BM / WMv);
    const int nbase  = wn * 32;

    const uint32_t smem_base = smem_to_u32(dsm);

    float acc[MT][4][4];
#pragma unroll
    for (int i = 0; i < MT; i++)
#pragma unroll
        for (int j = 0; j < 4; j++)
#pragma unroll
            for (int c = 0; c < 4; c++) acc[i][j][c] = 0.0f;

    auto load_stage = [&](int k0, int s) {
        uint32_t sb = smem_base + s * GST;
#pragma unroll
        for (int it = 0; it < NCHUNK; it++) {
            int e = tid + it * 256;
            if (e < 1024) {                 // A tile: 128 rows x 8 chunks
                int row = e >> 3, c = e & 7;
                cp16(sb + row * (LDT * 2) + c * 16,
                     A + (size_t)(m0 + row) * KDIM + k0 + c * 8);
            } else {                        // W tile: BNv rows x 8 chunks
                int rem = e - 1024;
                int row = rem >> 3, c = rem & 7;
                cp16(sb + GTILE_A + row * (LDT * 2) + c * 16,
                     W + (size_t)(n0 + row) * KDIM + k0 + c * 8);
            }
        }
        CP_COMMIT();
    };

    load_stage(0, 0);

    for (int i = 0; i < GNIT; i++) {
        CP_WAIT0();
        __syncthreads();
        if (i + 1 < GNIT) load_stage((i + 1) * BKK, (i + 1) & 1);

        const uint32_t sb = smem_base + (i & 1) * GST;
        const uint32_t uA = sb;
        const uint32_t uW = sb + GTILE_A;

#pragma unroll
        for (int ks = 0; ks < 4; ks++) {
            const int kcol = ks * 16 + kh * 8;

            uint32_t af[MT][4];
#pragma unroll
            for (int mt = 0; mt < MT; mt++) {
                int row = mbase + mt * 16 + lr + 8 * half2_;
                ldsm_x4(af[mt][0], af[mt][1], af[mt][2], af[mt][3],
                        uA + (uint32_t)(row * LDT + kcol) * 2);
            }
            uint32_t bf[4][2];
#pragma unroll
            for (int ntp = 0; ntp < 2; ntp++) {
                int row = nbase + ntp * 16 + lr + 8 * half2_;
                uint32_t r0, r1, r2, r3;
                ldsm_x4(r0, r1, r2, r3, uW + (uint32_t)(row * LDT + kcol) * 2);
                bf[ntp * 2 + 0][0] = r0; bf[ntp * 2 + 0][1] = r2;
                bf[ntp * 2 + 1][0] = r1; bf[ntp * 2 + 1][1] = r3;
            }
#pragma unroll
            for (int mt = 0; mt < MT; mt++)
#pragma unroll
                for (int nt = 0; nt < 4; nt++)
                    mma16816(acc[mt][nt], af[mt], bf[nt]);
        }
        __syncthreads();
    }

    const int erow = lid >> 2;
    const int ecol = (lid & 3) * 2;
#pragma unroll
    for (int mt = 0; mt < MT; mt++) {
#pragma unroll
        for (int nt = 0; nt < 4; nt++) {
            int gm = m0 + mbase + mt * 16 + erow;
            int nc = nbase + nt * 8 + ecol;
            int gn = n0 + nc;
            float v0 = (acc[mt][nt][0] + s_bias[nc])     * scale;
            float v1 = (acc[mt][nt][1] + s_bias[nc + 1]) * scale;
            float v2 = (acc[mt][nt][2] + s_bias[nc])     * scale;
            float v3 = (acc[mt][nt][3] + s_bias[nc + 1]) * scale;
            if (Ch) {
                *(uint32_t*)&Ch[(size_t)gm * D_MODEL + gn]       = packh2(v0, v1);
                *(uint32_t*)&Ch[(size_t)(gm + 8) * D_MODEL + gn] = packh2(v2, v3);
            } else {
                *(float2*)&Cf[(size_t)gm * D_MODEL + gn]       = make_float2(v0, v1);
                *(float2*)&Cf[(size_t)(gm + 8) * D_MODEL + gn] = make_float2(v2, v3);
            }
        }
    }
}

__global__ __launch_bounds__(256, 2)
void qk_gemm_kernel(const float* __restrict__ bq, const float* __restrict__ bk)
{
    if (blockIdx.z == 0)
        gemm_core<64>(g_Hh, g_Wqh, bq, QK_SCALE, nullptr, g_Qh);
    else
        gemm_core<64>(g_Hh, g_Wkh, bk, 1.0f, nullptr, g_Kh);
}

__global__ __launch_bounds__(256, 2)
void out_gemm_kernel(const float* __restrict__ bo, float* __restrict__ out)
{
    gemm_core<128>(g_AOh, g_Woh, bo, 1.0f, out, nullptr);
}

// ---------------------------------------------------------------------------
// HMMA flash attention, fine-grained (r16): CTA = 64 q-rows, 256 threads.
// Warps 0-3: keys [0,64) of each 128-key stage; warps 4-7: keys [64,128).
// grid (32, 32) = 1024 CTAs. 2-stage cp.async pipeline. Exact 2-way merge.
// ---------------------------------------------------------------------------
#define SLDT 72                        // 144 B row
#define AARR (128 * SLDT * 2)          // 18432 B per array (K or V)
#define AST  (2 * AARR)                // 36864 B per stage
#define NSTG (SEQ / 128)               // 16 stages

__global__ __launch_bounds__(256, 1)
void attn_mma_kernel()
{
    extern __shared__ char dsm[];
    __half* pool = (__half*)dsm;

    const int tid = threadIdx.x;
    const int wid = tid >> 5;
    const int lid = tid & 31;
    const int b   = blockIdx.x >> 4;
    const int h   = blockIdx.x & 15;
    const int q0  = blockIdx.y * 64;

    const int lr     = lid & 7;
    const int half2_ = (lid >> 3) & 1;
    const int kh     = (lid >> 4) & 1;
    const int wq     = wid & 3;
    const int sub    = wid >> 2;

    const uint32_t smem_base = smem_to_u32(dsm);

    // ---- stage Q tile (64 x 64) through stage-0 area, extract frags ----
#pragma unroll
    for (int i = 0; i < 2; i++) {
        int e   = tid + i * 256;            // 0..511
        int row = e >> 3;
        int c   = e & 7;
        const __half* src = g_Qh
            + (size_t)(b * SEQ + q0 + row) * D_MODEL + h * HDIM + c * 8;
        *(uint4*)(pool + row * SLDT + c * 8) = *(const uint4*)src;
    }
    __syncthreads();

    uint32_t qh[4][4];
    {
        const int wr = wq * 16;
#pragma unroll
        for (int kc = 0; kc < 4; kc++) {
            int row = wr + lr + 8 * half2_;
            int col = kc * 16 + kh * 8;
            ldsm_x4(qh[kc][0], qh[kc][1], qh[kc][2], qh[kc][3],
                    smem_base + (uint32_t)(row * SLDT + col) * 2);
        }
    }
    __syncthreads();

    float oacc[8][4];
#pragma unroll
    for (int nt = 0; nt < 8; nt++)
#pragma unroll
        for (int c = 0; c < 4; c++) oacc[nt][c] = 0.0f;
    float lacc[4] = {0.0f, 0.0f, 0.0f, 0.0f};
    float mx0 = -1e30f, mx1 = -1e30f;

    const uint32_t ones2[2] = {0x3C003C00u, 0x3C003C00u};

    auto load_stage = [&](int st, int s) {
        const int kb = st * 128;
        uint32_t sb = smem_base + s * AST;
#pragma unroll
        for (int i = 0; i < 8; i++) {
            int arr = i >> 2;                       // 0 K, 1 V
            int rem = ((i & 3) << 8) + tid;
            int row = rem >> 3;
            int c   = rem & 7;
            const __half* g = (arr == 0 ? g_Kh : g_Hh)
                + (size_t)(b * SEQ + kb + row) * D_MODEL + h * HDIM + c * 8;
            cp16(sb + arr * AARR + row * (SLDT * 2) + c * 16, g);
        }
        CP_COMMIT();
    };

    load_stage(0, 0);

    for (int st = 0; st < NSTG; st++) {
        CP_WAIT0();
        __syncthreads();
        if (st + 1 < NSTG) load_stage(st + 1, (st + 1) & 1);

        const uint32_t sbs = smem_base + (st & 1) * AST;
        const uint32_t uK = sbs + (uint32_t)(sub * 64 * SLDT) * 2;
        const uint32_t uV = sbs + AARR + (uint32_t)(sub * 64 * SLDT) * 2;

        // ---- S = Q K^T ----
        float S[8][4];
#pragma unroll
        for (int nt = 0; nt < 8; nt++)
#pragma unroll
            for (int c = 0; c < 4; c++) S[nt][c] = 0.0f;

#pragma unroll
        for (int kc = 0; kc < 4; kc++) {
            uint32_t kb_[8][2];
#pragma unroll
            for (int ng = 0; ng < 4; ng++) {
                int row = ng * 16 + lr + 8 * half2_;
                int col = kc * 16 + kh * 8;
                uint32_t r0, r1, r2, r3;
                ldsm_x4(r0, r1, r2, r3, uK + (uint32_t)(row * SLDT + col) * 2);
                kb_[ng * 2 + 0][0] = r0; kb_[ng * 2 + 0][1] = r2;
                kb_[ng * 2 + 1][0] = r1; kb_[ng * 2 + 1][1] = r3;
            }
#pragma unroll
            for (int nt = 0; nt < 8; nt++)
                mma16816(S[nt], qh[kc], kb_[nt]);
        }

        // ---- online softmax (voted conditional rescale) ----
        float tm0 = -1e30f, tm1 = -1e30f;
#pragma unroll
        for (int nt = 0; nt < 8; nt++) {
            tm0 = fmaxf(tm0, fmaxf(S[nt][0], S[nt][1]));
            tm1 = fmaxf(tm1, fmaxf(S[nt][2], S[nt][3]));
        }
        tm0 = fmaxf(tm0, __shfl_xor_sync(0xffffffffu, tm0, 1));
        tm0 = fmaxf(tm0, __shfl_xor_sync(0xffffffffu, tm0, 2));
        tm1 = fmaxf(tm1, __shfl_xor_sync(0xffffffffu, tm1, 1));
        tm1 = fmaxf(tm1, __shfl_xor_sync(0xffffffffu, tm1, 2));

        bool grew = (tm0 > mx0) || (tm1 > mx1);
        if (__any_sync(0xffffffffu, grew)) {
            float mn0 = fmaxf(mx0, tm0), mn1 = fmaxf(mx1, tm1);
            float a0 = ex2f(mx0 - mn0), a1 = ex2f(mx1 - mn1);
            lacc[0] *= a0; lacc[1] *= a0;
            lacc[2] *= a1; lacc[3] *= a1;
#pragma unroll
            for (int nt = 0; nt < 8; nt++) {
                oacc[nt][0] *= a0; oacc[nt][1] *= a0;
                oacc[nt][2] *= a1; oacc[nt][3] *= a1;
            }
            mx0 = mn0; mx1 = mn1;
        }

        // ---- P = exp2(S - mx) via f16x2 MUFU ----
        uint32_t pa[4][4];
#pragma unroll
        for (int j = 0; j < 4; j++) {
#pragma unroll
            for (int sg = 0; sg < 2; sg++) {
                int t2 = j * 2 + sg;
                pa[j][sg * 2 + 0] = h2exp2u(packh2(S[t2][0] - mx0, S[t2][1] - mx0));
                pa[j][sg * 2 + 1] = h2exp2u(packh2(S[t2][2] - mx1, S[t2][3] - mx1));
            }
        }

        // ---- O += P V ; l += P 1 ----
#pragma unroll
        for (int kc = 0; kc < 4; kc++) {
            uint32_t vb[8][2];
#pragma unroll
            for (int dg = 0; dg < 4; dg++) {
                int rowk = kc * 16 + lr + 8 * half2_;
                int dimc = dg * 16 + kh * 8;
                uint32_t r0, r1, r2, r3;
                ldsm_x4_t(r0, r1, r2, r3, uV + (uint32_t)(rowk * SLDT + dimc) * 2);
                vb[dg * 2 + 0][0] = r0; vb[dg * 2 + 0][1] = r1;
                vb[dg * 2 + 1][0] = r2; vb[dg * 2 + 1][1] = r3;
            }
            mma16816(lacc, pa[kc], ones2);
#pragma unroll
            for (int nt = 0; nt < 8; nt++)
                mma16816(oacc[nt], pa[kc], vb[nt]);
        }
    }

    // ---- merge warp-group halves (exact two-way softmax combine) ----
    __syncthreads();
    float* buf = (float*)dsm;
    if (wid >= 4) {
        int base = (tid - 128) * 36;
        buf[base + 0] = mx0; buf[base + 1] = mx1;
        buf[base + 2] = lacc[0]; buf[base + 3] = lacc[2];
#pragma unroll
        for (int nt = 0; nt < 8; nt++)
#pragma unroll
            for (int c = 0; c < 4; c++)
                buf[base + 4 + nt * 4 + c] = oacc[nt][c];
    }
    __syncthreads();

    if (wid < 4) {
        int base = tid * 36;
        float mB0 = buf[base + 0], mB1 = buf[base + 1];
        float lB0 = buf[base + 2], lB1 = buf[base + 3];
        float m0 = fmaxf(mx0, mB0), m1 = fmaxf(mx1, mB1);
        float wA0 = ex2f(mx0 - m0), wB0 = ex2f(mB0 - m0);
        float wA1 = ex2f(mx1 - m1), wB1 = ex2f(mB1 - m1);
        float inv0 = 1.0f / (lacc[0] * wA0 + lB0 * wB0);
        float inv1 = 1.0f / (lacc[2] * wA1 + lB1 * wB1);

        const int gr  = b * SEQ + q0 + wq * 16 + (lid >> 2);
        const int col = h * HDIM + (lid & 3) * 2;
#pragma unroll
        for (int nt = 0; nt < 8; nt++) {
            int gc = col + nt * 8;
            float v0 = (oacc[nt][0] * wA0 + buf[base + 4 + nt * 4 + 0] * wB0) * inv0;
            float v1 = (oacc[nt][1] * wA0 + buf[base + 4 + nt * 4 + 1] * wB0) * inv0;
            float v2 = (oacc[nt][2] * wA1 + buf[base + 4 + nt * 4 + 2] * wB1) * inv1;
            float v3 = (oacc[nt][3] * wA1 + buf[base + 4 + nt * 4 + 3] * wB1) * inv1;
            *(uint32_t*)&g_AOh[(size_t)gr * D_MODEL + gc]       = packh2(v0, v1);
            *(uint32_t*)&g_AOh[(size_t)(gr + 8) * D_MODEL + gc] = packh2(v2, v3);
        }
    }
}

// ---------------------------------------------------------------------------
extern "C" void kernel_launch(void* const* d_in, const int* in_sizes, int n_in,
                              void* d_out, int out_size)
{
    (void)in_sizes; (void)n_in; (void)out_size;
    const float* H  = (const float*)d_in[0];
    const float* Wq = (const float*)d_in[1];
    const float* bq = (const float*)d_in[2];
    const float* Wk = (const float*)d_in[3];
    const float* bk = (const float*)d_in[4];
    const float* Wo = (const float*)d_in[5];
    const float* bo = (const float*)d_in[6];
    float* out = (float*)d_out;

    void *p_Hh, *p_Wqh, *p_Wkh, *p_Woh;
    cudaGetSymbolAddress(&p_Hh,  g_Hh);
    cudaGetSymbolAddress(&p_Wqh, g_Wqh);
    cudaGetSymbolAddress(&p_Wkh, g_Wkh);
    cudaGetSymbolAddress(&p_Woh, g_Woh);

    const int GSMEM_QK  = 2 * (GTILE_A + 64 * LDT * 2);    // 55,296 B
    const int GSMEM_OUT = 2 * (GTILE_A + 128 * LDT * 2);   // 73,728 B
    const int ASMEM     = 2 * AST;                          // 73,728 B

    cudaFuncSetAttribute(qk_gemm_kernel,
                         cudaFuncAttributeMaxDynamicSharedMemorySize, GSMEM_QK);
    cudaFuncSetAttribute(out_gemm_kernel,
                         cudaFuncAttributeMaxDynamicSharedMemorySize, GSMEM_OUT);
    cudaFuncSetAttribute(attn_mma_kernel,
                         cudaFuncAttributeMaxDynamicSharedMemorySize, ASMEM);

    const int nH4 = NROWS * D_MODEL / 4;      // 1,048,576
    const int nW4 = D_MODEL * D_MODEL / 4;    // 262,144
    const int nTot = nH4 + 3 * nW4;           // 1,835,008

    cast4_kernel<<<(nTot + 255) / 256, 256>>>(
        (const float4*)H,  (uint2*)p_Hh,  nH4,
        (const float4*)Wq, (uint2*)p_Wqh, nW4,
        (const float4*)Wk, (uint2*)p_Wkh, nW4,
        (const float4*)Wo, (uint2*)p_Woh, nW4);

    dim3 qgrid(D_MODEL / 64, NROWS / BM, 2);   // (16, 32, 2) = 1024 CTAs
    qk_gemm_kernel<<<qgrid, 256, GSMEM_QK>>>(bq, bk);

    dim3 agrid(BATCH * NHEADS, SEQ / 64);      // (32, 32) = 1024 CTAs
    attn_mma_kernel<<<agrid, 256, ASMEM>>>();

    dim3 ogrid(D_MODEL / 128, NROWS / BM, 1);  // (8, 32) = 256 CTAs
    out_gemm_kernel<<<ogrid, 256, GSMEM_OUT>>>(bo, out);
}